// round 13
// baseline (speedup 1.0000x reference)
#include <cuda_runtime.h>
#include <cuda_bf16.h>
#include <mma.h>
#include <cstddef>

using namespace nvcuda;

#define NN 50000
#define EE 600000
#define GG 512
#define MM 2048
#define DD 128
#define FFN 256
#define LL 3
#define BN_EPS 1e-5f
#define SCAN_B 196   // ceil(NN/256)
#define LDP 72       // padded bf16 row length (144B) -> conflict-free ldmatrix

// ---------------- scratch (device globals) ----------------
__device__ float g_bufA[NN * DD];   // layer output h (raw, pre-BN)
__device__ float g_bufB[NN * DD];   // hw branch
__device__ float g_bufR[NN * DD];   // residual branch
__device__ int   g_degin[NN];
__device__ int   g_degout[NN];
__device__ int   g_cursor[NN];
__device__ int   g_rowstart[NN + 1];
__device__ int   g_csr_src[EE];
__device__ int   g_bsum[SCAN_B];
__device__ int   g_boff[SCAN_B];
__device__ float g_norm_src[NN];
__device__ float g_norm_dst[NN];
__device__ float g_stats[2 * DD];
__device__ float g_cs[DD];
__device__ float g_cb[DD];
__device__ float g_zero[DD];
__device__ float g_wp1[DD * DD];    // cs-scaled Wg[l]
__device__ float g_wp2[DD * DD];    // cs-scaled Wr[l]
__device__ float g_bc1[DD];         // cb @ Wg[l]
__device__ float g_bc2[DD];         // cb @ Wr[l] + br[l]
__device__ float g_gsum[GG * DD];
__device__ float g_gcnt[GG];
__device__ float g_msum[(MM + 1) * DD];
__device__ float g_mcnt[MM + 1];
__device__ float g_headin[(GG + MM) * DD];
__device__ float g_head1[(GG + MM) * FFN];
__device__ float g_head2[(GG + MM) * FFN];

// ---------------- f32x2 helpers (head GEMM) ----------------
__device__ __forceinline__ unsigned long long pack_dup(float x) {
    unsigned long long p;
    unsigned int xb = __float_as_uint(x);
    asm("mov.b64 %0, {%1, %1};" : "=l"(p) : "r"(xb));
    return p;
}
__device__ __forceinline__ void ffma2(unsigned long long& acc, unsigned long long a,
                                      unsigned long long b) {
    asm("fma.rn.f32x2 %0, %1, %2, %0;" : "+l"(acc) : "l"(a), "l"(b));
}
__device__ __forceinline__ float2 unpack2(unsigned long long a) {
    float lo, hi;
    asm("mov.b64 {%0, %1}, %2;" : "=f"(lo), "=f"(hi) : "l"(a));
    return make_float2(lo, hi);
}

// ---------------- bf16 hi/lo split store (4 values) ----------------
__device__ __forceinline__ void split_store(__nv_bfloat16* ph, __nv_bfloat16* pl, float4 v) {
    __nv_bfloat162 h01 = __floats2bfloat162_rn(v.x, v.y);
    __nv_bfloat162 h23 = __floats2bfloat162_rn(v.z, v.w);
    float2 f01 = __bfloat1622float2(h01);
    float2 f23 = __bfloat1622float2(h23);
    __nv_bfloat162 l01 = __floats2bfloat162_rn(v.x - f01.x, v.y - f01.y);
    __nv_bfloat162 l23 = __floats2bfloat162_rn(v.z - f23.x, v.w - f23.y);
    uint2 hv, lv;
    hv.x = *(unsigned*)&h01; hv.y = *(unsigned*)&h23;
    lv.x = *(unsigned*)&l01; lv.y = *(unsigned*)&l23;
    *(uint2*)ph = hv;
    *(uint2*)pl = lv;
}

// ---------------- setup ----------------
__global__ void k_zero() {
    int i = blockIdx.x * blockDim.x + threadIdx.x;
    if (i < NN) { g_degin[i] = 0; g_degout[i] = 0; }
}

__global__ void k_hist(const int* __restrict__ src, const int* __restrict__ dst) {
    int e = blockIdx.x * blockDim.x + threadIdx.x;
    if (e < EE) {
        atomicAdd(&g_degout[src[e]], 1);
        atomicAdd(&g_degin[dst[e]], 1);
    }
}

__global__ void k_norms() {
    int i = blockIdx.x * blockDim.x + threadIdx.x;
    if (i < NN) {
        g_norm_src[i] = rsqrtf(fmaxf((float)g_degout[i], 1.0f));
        g_norm_dst[i] = rsqrtf(fmaxf((float)g_degin[i], 1.0f));
    }
    if (i < 2 * DD) g_stats[i] = 0.f;
    if (i < DD) g_zero[i] = 0.f;
}

// ---------------- multi-block scan of g_degin -> g_rowstart ----------------
__global__ void k_scan1() {
    __shared__ int sh[256];
    int tid = threadIdx.x;
    int i = blockIdx.x * 256 + tid;
    int v = (i < NN) ? g_degin[i] : 0;
    if (i < NN) g_cursor[i] = 0;
    sh[tid] = v;
    __syncthreads();
    for (int off = 128; off > 0; off >>= 1) {
        if (tid < off) sh[tid] += sh[tid + off];
        __syncthreads();
    }
    if (tid == 0) g_bsum[blockIdx.x] = sh[0];
}

__global__ void k_scan2() {
    __shared__ int sh[256];
    int tid = threadIdx.x;
    int v = (tid < SCAN_B) ? g_bsum[tid] : 0;
    sh[tid] = v;
    __syncthreads();
    for (int off = 1; off < 256; off <<= 1) {
        int t = (tid >= off) ? sh[tid - off] : 0;
        __syncthreads();
        sh[tid] += t;
        __syncthreads();
    }
    if (tid < SCAN_B) g_boff[tid] = sh[tid] - v;
}

__global__ void k_scan3() {
    __shared__ int sh[256];
    int tid = threadIdx.x;
    int i = blockIdx.x * 256 + tid;
    int v = (i < NN) ? g_degin[i] : 0;
    sh[tid] = v;
    __syncthreads();
    for (int off = 1; off < 256; off <<= 1) {
        int t = (tid >= off) ? sh[tid - off] : 0;
        __syncthreads();
        sh[tid] += t;
        __syncthreads();
    }
    if (i < NN) g_rowstart[i] = sh[tid] - v + g_boff[blockIdx.x];
    if (blockIdx.x == 0 && tid == 0) g_rowstart[NN] = EE;
}

__global__ void k_place(const int* __restrict__ src, const int* __restrict__ dst) {
    int e = blockIdx.x * blockDim.x + threadIdx.x;
    if (e < EE) {
        int d = dst[e];
        int slot = atomicAdd(&g_cursor[d], 1);
        g_csr_src[g_rowstart[d] + slot] = src[e];
    }
}

// ---------------- BN-affine weight prep (layers 1,2) ----------------
__global__ void k_wprep(const float* __restrict__ W1, const float* __restrict__ W2) {
    int k = blockIdx.x, c = threadIdx.x;
    float s = g_cs[k];
    g_wp1[k * DD + c] = s * W1[k * DD + c];
    g_wp2[k * DD + c] = s * W2[k * DD + c];
}

__global__ void k_wbias(const float* __restrict__ W1, const float* __restrict__ W2,
                        const float* __restrict__ br) {
    int tid = threadIdx.x;   // 256
    int c = tid & (DD - 1);
    const float* W = (tid < DD) ? W1 : W2;
    float s = 0.f;
#pragma unroll 16
    for (int k = 0; k < DD; k++) s += g_cb[k] * W[k * DD + c];
    if (tid < DD) g_bc1[c] = s;
    else          g_bc2[c] = s + br[c];
}

// ---------------- dual GEMM: split-bf16 tensor cores, 512 threads / 16 warps ----------------
// Y1 = rs .* (X @ W1 + b1c);  Y2 = relu(X @ W2 + b2c)
// Tile 128 rows x 64 cols; 16 warps (4m x 4n), each 32 rows x 16 cols x 2 matrices.
__global__ void __launch_bounds__(512)
k_dualgemm(const float* __restrict__ X,
           const float* __restrict__ W1f,
           const float* __restrict__ W2f,
           const float* __restrict__ b1c,
           const float* __restrict__ b2c,
           const float* __restrict__ rs,
           float* __restrict__ Y1, float* __restrict__ Y2,
           int nrows) {
    extern __shared__ __nv_bfloat16 smb[];
    __nv_bfloat16* W1h = smb;                    // 128*LDP each (18 KB)
    __nv_bfloat16* W1l = W1h + 128 * LDP;
    __nv_bfloat16* W2h = W1l + 128 * LDP;
    __nv_bfloat16* W2l = W2h + 128 * LDP;
    __nv_bfloat16* Xh  = W2l + 128 * LDP;
    __nv_bfloat16* Xl  = Xh + 128 * LDP;
    float* stage = (float*)Xh;

    const int tid = threadIdx.x;
    const int w = tid >> 5;
    const int wr = (w & 3) * 32;       // 4 m-groups
    const int wc = (w >> 2) * 16;      // 4 n-groups
    const int r0 = blockIdx.x * 128;
    const int c0 = blockIdx.y * 64;

    // prefetch X chunk 0 (k 0..63): 2048 float4 over 512 threads = 4 each
    float4 xreg[4];
#pragma unroll
    for (int i = 0; i < 4; i++) {
        int f = tid + 512 * i;
        int rl = f >> 4, j4 = f & 15;
        int row = r0 + rl;
        xreg[i] = make_float4(0.f, 0.f, 0.f, 0.f);
        if (row < nrows) xreg[i] = *(const float4*)&X[(size_t)row * DD + j4 * 4];
    }

    // convert W tiles once: 2048 float4 each matrix, 4 per thread
#pragma unroll
    for (int i = 0; i < 4; i++) {
        int f = tid + 512 * i;
        int k = f >> 4, c4 = f & 15;
        float4 v1 = ((const float4*)&W1f[(size_t)k * DD + c0])[c4];
        float4 v2 = ((const float4*)&W2f[(size_t)k * DD + c0])[c4];
        split_store(W1h + k * LDP + c4 * 4, W1l + k * LDP + c4 * 4, v1);
        split_store(W2h + k * LDP + c4 * 4, W2l + k * LDP + c4 * 4, v2);
    }

    wmma::fragment<wmma::accumulator, 16, 16, 16, float> acc1[2], acc2[2];
#pragma unroll
    for (int i = 0; i < 2; i++) {
        wmma::fill_fragment(acc1[i], 0.f);
        wmma::fill_fragment(acc2[i], 0.f);
    }

#pragma unroll 1
    for (int kc = 0; kc < 2; kc++) {
        __syncthreads();   // W stores visible (kc=0) / prior Xs readers done (kc=1)
#pragma unroll
        for (int i = 0; i < 4; i++) {
            int f = tid + 512 * i;
            int rl = f >> 4, j4 = f & 15;
            split_store(Xh + rl * LDP + j4 * 4, Xl + rl * LDP + j4 * 4, xreg[i]);
        }
        if (kc == 0) {
            // prefetch chunk 1 (k 64..127)
#pragma unroll
            for (int i = 0; i < 4; i++) {
                int f = tid + 512 * i;
                int rl = f >> 4, j4 = f & 15;
                int row = r0 + rl;
                xreg[i] = make_float4(0.f, 0.f, 0.f, 0.f);
                if (row < nrows) xreg[i] = *(const float4*)&X[(size_t)row * DD + 64 + j4 * 4];
            }
        }
        __syncthreads();

#pragma unroll
        for (int ks = 0; ks < 64; ks += 16) {
            wmma::fragment<wmma::matrix_a, 16, 16, 16, __nv_bfloat16, wmma::row_major> ah[2], al[2];
#pragma unroll
            for (int i = 0; i < 2; i++) {
                wmma::load_matrix_sync(ah[i], Xh + (wr + 16 * i) * LDP + ks, LDP);
                wmma::load_matrix_sync(al[i], Xl + (wr + 16 * i) * LDP + ks, LDP);
            }
            int kg = kc * 64 + ks;
            wmma::fragment<wmma::matrix_b, 16, 16, 16, __nv_bfloat16, wmma::row_major> bh, bl;
            wmma::load_matrix_sync(bh, W1h + kg * LDP + wc, LDP);
            wmma::load_matrix_sync(bl, W1l + kg * LDP + wc, LDP);
#pragma unroll
            for (int i = 0; i < 2; i++) {
                wmma::mma_sync(acc1[i], ah[i], bh, acc1[i]);
                wmma::mma_sync(acc1[i], ah[i], bl, acc1[i]);
                wmma::mma_sync(acc1[i], al[i], bh, acc1[i]);
            }
            wmma::load_matrix_sync(bh, W2h + kg * LDP + wc, LDP);
            wmma::load_matrix_sync(bl, W2l + kg * LDP + wc, LDP);
#pragma unroll
            for (int i = 0; i < 2; i++) {
                wmma::mma_sync(acc2[i], ah[i], bh, acc2[i]);
                wmma::mma_sync(acc2[i], ah[i], bl, acc2[i]);
                wmma::mma_sync(acc2[i], al[i], bh, acc2[i]);
            }
        }
    }

    // ---- epilogue via fp32 staging (reuses X smem) ----
    __syncthreads();
#pragma unroll
    for (int i = 0; i < 2; i++)
        wmma::store_matrix_sync(stage + (wr + 16 * i) * LDP + wc,
                                acc1[i], LDP, wmma::mem_row_major);
    __syncthreads();
#pragma unroll
    for (int i = 0; i < 4; i++) {
        int f = tid + 512 * i;
        int rl = f >> 4, c4 = f & 15;
        int row = r0 + rl;
        if (row < nrows) {
            float s = rs[row];
            float4 vv = *(const float4*)&stage[rl * LDP + c4 * 4];
            float4 bb = ((const float4*)&b1c[c0])[c4];
            float4 o;
            o.x = (vv.x + bb.x) * s; o.y = (vv.y + bb.y) * s;
            o.z = (vv.z + bb.z) * s; o.w = (vv.w + bb.w) * s;
            ((float4*)&Y1[(size_t)row * DD + c0])[c4] = o;
        }
    }
    __syncthreads();
#pragma unroll
    for (int i = 0; i < 2; i++)
        wmma::store_matrix_sync(stage + (wr + 16 * i) * LDP + wc,
                                acc2[i], LDP, wmma::mem_row_major);
    __syncthreads();
#pragma unroll
    for (int i = 0; i < 4; i++) {
        int f = tid + 512 * i;
        int rl = f >> 4, c4 = f & 15;
        int row = r0 + rl;
        if (row < nrows) {
            float4 vv = *(const float4*)&stage[rl * LDP + c4 * 4];
            float4 bb = ((const float4*)&b2c[c0])[c4];
            float4 o;
            o.x = fmaxf(vv.x + bb.x, 0.f);
            o.y = fmaxf(vv.y + bb.y, 0.f);
            o.z = fmaxf(vv.z + bb.z, 0.f);
            o.w = fmaxf(vv.w + bb.w, 0.f);
            ((float4*)&Y2[(size_t)row * DD + c0])[c4] = o;
        }
    }
}

// ---------------- CSR aggregation + combine + BN stats (+ pooling on last layer) ----------------
__global__ void k_agg(const float* __restrict__ bg, int zpool, int do_pool,
                      const int* __restrict__ gid, const int* __restrict__ mid) {
    __shared__ float ssum[8][DD];
    __shared__ float ssq[8][DD];
    int tid = threadIdx.x;
    int w = tid >> 5;
    int lane = tid & 31;

    if (zpool) {
        int gstep = gridDim.x * blockDim.x;
        int gidx = blockIdx.x * blockDim.x + tid;
        for (int i = gidx; i < GG * DD; i += gstep) g_gsum[i] = 0.f;
        for (int i = gidx; i < (MM + 1) * DD; i += gstep) g_msum[i] = 0.f;
        for (int i = gidx; i < GG; i += gstep) g_gcnt[i] = 0.f;
        for (int i = gidx; i < MM + 1; i += gstep) g_mcnt[i] = 0.f;
    }

    int node = blockIdx.x * 8 + w;
    float4 y = make_float4(0.f, 0.f, 0.f, 0.f);
    if (node < NN) {
        int e0 = g_rowstart[node], e1 = g_rowstart[node + 1];
        float4 acc[4];
#pragma unroll
        for (int i = 0; i < 4; i++) acc[i] = make_float4(0.f, 0.f, 0.f, 0.f);

        for (int base = e0; base < e1; base += 16) {
            int n = e1 - base;
            float4 v[16];
#pragma unroll
            for (int i = 0; i < 16; i++) {
                v[i] = make_float4(0.f, 0.f, 0.f, 0.f);
                if (i < n) {
                    int s = g_csr_src[base + i];
                    v[i] = ((const float4*)(g_bufB + (size_t)s * DD))[lane];
                }
            }
#pragma unroll
            for (int i = 0; i < 16; i++) {
                acc[i & 3].x += v[i].x; acc[i & 3].y += v[i].y;
                acc[i & 3].z += v[i].z; acc[i & 3].w += v[i].w;
            }
        }
        acc[0].x += acc[1].x + acc[2].x + acc[3].x;
        acc[0].y += acc[1].y + acc[2].y + acc[3].y;
        acc[0].z += acc[1].z + acc[2].z + acc[3].z;
        acc[0].w += acc[1].w + acc[2].w + acc[3].w;

        float nd = g_norm_dst[node];
        float4 b4 = ((const float4*)bg)[lane];
        float4 r = ((const float4*)(g_bufR + (size_t)node * DD))[lane];
        y.x = fmaxf(fmaf(acc[0].x, nd, b4.x), 0.f) + r.x;
        y.y = fmaxf(fmaf(acc[0].y, nd, b4.y), 0.f) + r.y;
        y.z = fmaxf(fmaf(acc[0].z, nd, b4.z), 0.f) + r.z;
        y.w = fmaxf(fmaf(acc[0].w, nd, b4.w), 0.f) + r.w;

        if (do_pool) {
            int gi = gid[node], mi = mid[node];
            atomicAdd(((float4*)(g_gsum + (size_t)gi * DD)) + lane, y);
            atomicAdd(((float4*)(g_msum + (size_t)mi * DD)) + lane, y);
            if (lane == 0) {
                atomicAdd(&g_gcnt[gi], 1.0f);
                atomicAdd(&g_mcnt[mi], 1.0f);
            }
        } else {
            ((float4*)(g_bufA + (size_t)node * DD))[lane] = y;
        }
    }
    ((float4*)&ssum[w][0])[lane] = y;
    float4 y2 = make_float4(y.x * y.x, y.y * y.y, y.z * y.z, y.w * y.w);
    ((float4*)&ssq[w][0])[lane] = y2;
    __syncthreads();
    if (tid < DD) {
        float s = 0.f;
#pragma unroll
        for (int i = 0; i < 8; i++) s += ssum[i][tid];
        atomicAdd(&g_stats[tid], s);
    } else {
        int j = tid - DD;
        float s = 0.f;
#pragma unroll
        for (int i = 0; i < 8; i++) s += ssq[i][j];
        atomicAdd(&g_stats[DD + j], s);
    }
}

// ---------------- BN prep ----------------
__global__ void k_bnprep(const float* __restrict__ gamma, const float* __restrict__ beta) {
    int j = threadIdx.x;
    float invN = 1.0f / (float)NN;
    float mu = g_stats[j] * invN;
    float var = fmaxf(g_stats[DD + j] * invN - mu * mu, 0.f);
    float s = gamma[j] * rsqrtf(var + BN_EPS);
    g_cs[j] = s;
    g_cb[j] = beta[j] - mu * s;
    g_stats[j] = 0.f;
    g_stats[DD + j] = 0.f;
}

// ---------------- finalize: mean pools + layer-2 BN affine ----------------
__global__ void k_finalize(float* __restrict__ out_gf) {
    int idx = blockIdx.x * blockDim.x + threadIdx.x;
    if (idx >= (GG + MM) * DD) return;
    int row = idx / DD, j = idx % DD;
    float cs = g_cs[j], cb = g_cb[j];
    float v;
    if (row < GG) {
        v = cs * g_gsum[row * DD + j] / fmaxf(g_gcnt[row], 1.0f) + cb;
        out_gf[row * DD + j] = v;
    } else {
        int mrow = row - GG + 1;
        v = cs * g_msum[mrow * DD + j] / fmaxf(g_mcnt[mrow], 1.0f) + cb;
    }
    g_headin[idx] = v;
}

// ---------------- fp32 tiled GEMM with f32x2 (head MLP) ----------------
__global__ void k_gemm(const float* __restrict__ X, const float* __restrict__ W,
                       const float* __restrict__ bias,
                       float* __restrict__ Y, int nrows, int K, int ncols, int do_relu) {
    extern __shared__ float sm[];
    float* Ws = sm;
    float* Xs = sm + 128 * 128;
    const int tid = threadIdx.x;
    const int tx = tid & 31;
    const int ty = tid >> 5;
    const int r0 = blockIdx.x * 64;
    const int c0 = blockIdx.y * 128;

    unsigned long long acc[8][2];
#pragma unroll
    for (int m = 0; m < 8; m++) acc[m][0] = acc[m][1] = 0ull;

    for (int kb = 0; kb < K; kb += 128) {
#pragma unroll
        for (int i = 0; i < 16; i++) {
            int f = tid + 256 * i;
            int r = f >> 5, c4 = f & 31;
            ((float4*)Ws)[f] = *(const float4*)&W[(size_t)(kb + r) * ncols + c0 + c4 * 4];
        }
#pragma unroll
        for (int i = 0; i < 8; i++) {
            int f = tid + 256 * i;
            int m = f >> 5, k4 = f & 31;
            int row = r0 + m;
            float4 v = make_float4(0.f, 0.f, 0.f, 0.f);
            if (row < nrows) v = *(const float4*)&X[(size_t)row * K + kb + k4 * 4];
            ((float4*)Xs)[f] = v;
        }
        __syncthreads();

#pragma unroll 2
        for (int k = 0; k < 128; k += 4) {
            float4 xv[8];
#pragma unroll
            for (int m = 0; m < 8; m++)
                xv[m] = *(const float4*)&Xs[(ty * 8 + m) * 128 + k];
#pragma unroll
            for (int kk = 0; kk < 4; kk++) {
                ulonglong2 w = *(const ulonglong2*)&Ws[(k + kk) * 128 + tx * 4];
#pragma unroll
                for (int m = 0; m < 8; m++) {
                    float x = (kk == 0) ? xv[m].x : (kk == 1) ? xv[m].y
                            : (kk == 2) ? xv[m].z : xv[m].w;
                    unsigned long long xp = pack_dup(x);
                    ffma2(acc[m][0], xp, w.x);
                    ffma2(acc[m][1], xp, w.y);
                }
            }
        }
        __syncthreads();
    }

    float4 b4 = make_float4(0.f, 0.f, 0.f, 0.f);
    if (bias) b4 = *(const float4*)&bias[c0 + tx * 4];
#pragma unroll
    for (int m = 0; m < 8; m++) {
        int row = r0 + ty * 8 + m;
        if (row < nrows) {
            float2 p0 = unpack2(acc[m][0]);
            float2 p1 = unpack2(acc[m][1]);
            float4 o;
            o.x = p0.x + b4.x; o.y = p0.y + b4.y;
            o.z = p1.x + b4.z; o.w = p1.y + b4.w;
            if (do_relu) {
                o.x = fmaxf(o.x, 0.f); o.y = fmaxf(o.y, 0.f);
                o.z = fmaxf(o.z, 0.f); o.w = fmaxf(o.w, 0.f);
            }
            *(float4*)&Y[(size_t)row * ncols + c0 + tx * 4] = o;
        }
    }
}

// ---------------- launch ----------------
extern "C" void kernel_launch(void* const* d_in, const int* in_sizes, int n_in,
                              void* d_out, int out_size) {
    const float* node_feats = (const float*)d_in[0];
    const int*   src        = (const int*)d_in[1];
    const int*   dst        = (const int*)d_in[2];
    const int*   gid        = (const int*)d_in[3];
    const int*   mid        = (const int*)d_in[4];
    const float* Wg         = (const float*)d_in[5];
    const float* bg         = (const float*)d_in[6];
    const float* Wr         = (const float*)d_in[7];
    const float* br         = (const float*)d_in[8];
    const float* gamma      = (const float*)d_in[9];
    const float* beta       = (const float*)d_in[10];
    const float* W_feat     = (const float*)d_in[11];
    const float* b_feat     = (const float*)d_in[12];
    const float* W1         = (const float*)d_in[13];
    const float* b1         = (const float*)d_in[14];
    const float* W2         = (const float*)d_in[15];
    const float* b2         = (const float*)d_in[16];
    float* out = (float*)d_out;

    void *pA, *pns, *phin, *ph1, *ph2, *pB, *pR, *pwp1, *pwp2, *pbc1, *pbc2, *pz;
    cudaGetSymbolAddress(&pA, g_bufA);
    cudaGetSymbolAddress(&pB, g_bufB);
    cudaGetSymbolAddress(&pR, g_bufR);
    cudaGetSymbolAddress(&pns, g_norm_src);
    cudaGetSymbolAddress(&phin, g_headin);
    cudaGetSymbolAddress(&ph1, g_head1);
    cudaGetSymbolAddress(&ph2, g_head2);
    cudaGetSymbolAddress(&pwp1, g_wp1);
    cudaGetSymbolAddress(&pwp2, g_wp2);
    cudaGetSymbolAddress(&pbc1, g_bc1);
    cudaGetSymbolAddress(&pbc2, g_bc2);
    cudaGetSymbolAddress(&pz, g_zero);

    const int SMEM_G = (128 * 128 + 64 * 128) * 4;   // 96 KB (head gemm)
    const int SMEM_D = 6 * 128 * LDP * 2;            // 110592 B (dual gemm, bf16 split)
    cudaFuncSetAttribute(k_gemm, cudaFuncAttributeMaxDynamicSharedMemorySize, SMEM_G);
    cudaFuncSetAttribute(k_dualgemm, cudaFuncAttributeMaxDynamicSharedMemorySize, SMEM_D);

    const int gemm_rows = (NN + 127) / 128;   // 391
    const int agg_blocks = (NN + 7) / 8;      // 6250

    // ---- setup ----
    k_zero<<<(NN + 255) / 256, 256>>>();
    k_hist<<<(EE + 255) / 256, 256>>>(src, dst);
    k_norms<<<(NN + 255) / 256, 256>>>();

    // ---- layer-0 dual GEMM (4th launch, ncu-captured): raw weights, b1c=0, b2c=br ----
    k_dualgemm<<<dim3(gemm_rows, 2), 512, SMEM_D>>>(
        node_feats, Wg, Wr, (const float*)pz, br, (const float*)pns,
        (float*)pB, (float*)pR, NN);

    // ---- CSR build (stream-ordered before k_agg) ----
    k_scan1<<<SCAN_B, 256>>>();
    k_scan2<<<1, 256>>>();
    k_scan3<<<SCAN_B, 256>>>();
    k_place<<<(EE + 255) / 256, 256>>>(src, dst);

    for (int l = 0; l < LL; l++) {
        if (l > 0) {
            k_wprep<<<DD, DD>>>(Wg + (size_t)l * DD * DD, Wr + (size_t)l * DD * DD);
            k_wbias<<<1, 2 * DD>>>(Wg + (size_t)l * DD * DD, Wr + (size_t)l * DD * DD,
                                   br + (size_t)l * DD);
            k_dualgemm<<<dim3(gemm_rows, 2), 512, SMEM_D>>>(
                (const float*)pA, (const float*)pwp1, (const float*)pwp2,
                (const float*)pbc1, (const float*)pbc2, (const float*)pns,
                (float*)pB, (float*)pR, NN);
        }

        k_agg<<<agg_blocks, 256>>>(bg + (size_t)l * DD,
                                   (l == 0) ? 1 : 0,
                                   (l == LL - 1) ? 1 : 0,
                                   gid, mid);

        k_bnprep<<<1, DD>>>(gamma + (size_t)l * DD, beta + (size_t)l * DD);
    }

    // ---- finalize: mean pools + layer-2 BN affine ----
    k_finalize<<<((GG + MM) * DD + 255) / 256, 256>>>(out);

    // ---- head MLP on [graph_feats ; h_sub] = 2560 rows ----
    const int HR = GG + MM;
    const int hblocks = (HR + 63) / 64;
    k_gemm<<<dim3(hblocks, FFN / 128), 256, SMEM_G>>>(
        (const float*)phin, W_feat, b_feat, (float*)ph1, HR, DD, FFN, 0);
    k_gemm<<<dim3(hblocks, FFN / 128), 256, SMEM_G>>>(
        (const float*)ph1, W1, b1, (float*)ph2, HR, FFN, FFN, 1);
    k_gemm<<<dim3(hblocks, 1), 256, SMEM_G>>>(
        (const float*)ph2, W2, b2, out + (size_t)GG * DD, HR, FFN, DD, 0);
}

// round 14
// speedup vs baseline: 1.0041x; 1.0041x over previous
#include <cuda_runtime.h>
#include <cuda_bf16.h>
#include <mma.h>
#include <cstddef>

using namespace nvcuda;

#define NN 50000
#define EE 600000
#define GG 512
#define MM 2048
#define DD 128
#define FFN 256
#define LL 3
#define BN_EPS 1e-5f
#define SCAN_B 196   // ceil(NN/256)
#define LDP 72       // padded bf16 row length (144B) -> conflict-free ldmatrix

// ---------------- scratch (device globals) ----------------
__device__ float g_bufB[NN * DD];   // hw branch
__device__ float g_bufR[NN * DD];   // residual branch
__device__ __nv_bfloat16 g_xh[NN * DD];   // X hi (gemm input)
__device__ __nv_bfloat16 g_xl[NN * DD];   // X lo
__device__ __nv_bfloat16 g_w1h[DD * DD], g_w1l[DD * DD];
__device__ __nv_bfloat16 g_w2h[DD * DD], g_w2l[DD * DD];
__device__ int   g_degin[NN];
__device__ int   g_degout[NN];
__device__ int   g_cursor[NN];
__device__ int   g_rowstart[NN + 1];
__device__ int   g_csr_src[EE];
__device__ int   g_bsum[SCAN_B];
__device__ int   g_boff[SCAN_B];
__device__ float g_norm_src[NN];
__device__ float g_norm_dst[NN];
__device__ float g_stats[2 * DD];
__device__ float g_cs[DD];
__device__ float g_cb[DD];
__device__ float g_zero[DD];
__device__ float g_bc1[DD];         // cb @ Wg[l]
__device__ float g_bc2[DD];         // cb @ Wr[l] + br[l]
__device__ float g_gsum[GG * DD];
__device__ float g_gcnt[GG];
__device__ float g_msum[(MM + 1) * DD];
__device__ float g_mcnt[MM + 1];
__device__ float g_headin[(GG + MM) * DD];
__device__ float g_head1[(GG + MM) * FFN];
__device__ float g_head2[(GG + MM) * FFN];

// ---------------- helpers ----------------
__device__ __forceinline__ unsigned long long pack_dup(float x) {
    unsigned long long p;
    unsigned int xb = __float_as_uint(x);
    asm("mov.b64 %0, {%1, %1};" : "=l"(p) : "r"(xb));
    return p;
}
__device__ __forceinline__ void ffma2(unsigned long long& acc, unsigned long long a,
                                      unsigned long long b) {
    asm("fma.rn.f32x2 %0, %1, %2, %0;" : "+l"(acc) : "l"(a), "l"(b));
}
__device__ __forceinline__ float2 unpack2(unsigned long long a) {
    float lo, hi;
    asm("mov.b64 {%0, %1}, %2;" : "=f"(lo), "=f"(hi) : "l"(a));
    return make_float2(lo, hi);
}
__device__ __forceinline__ void split_store(__nv_bfloat16* ph, __nv_bfloat16* pl, float4 v) {
    __nv_bfloat162 h01 = __floats2bfloat162_rn(v.x, v.y);
    __nv_bfloat162 h23 = __floats2bfloat162_rn(v.z, v.w);
    float2 f01 = __bfloat1622float2(h01);
    float2 f23 = __bfloat1622float2(h23);
    __nv_bfloat162 l01 = __floats2bfloat162_rn(v.x - f01.x, v.y - f01.y);
    __nv_bfloat162 l23 = __floats2bfloat162_rn(v.z - f23.x, v.w - f23.y);
    uint2 hv, lv;
    hv.x = *(unsigned*)&h01; hv.y = *(unsigned*)&h23;
    lv.x = *(unsigned*)&l01; lv.y = *(unsigned*)&l23;
    *(uint2*)ph = hv;
    *(uint2*)pl = lv;
}
__device__ __forceinline__ void cp_async16(unsigned smem_addr, const void* gptr, bool valid) {
    int sz = valid ? 16 : 0;
    asm volatile("cp.async.cg.shared.global [%0], [%1], 16, %2;\n"
                 :: "r"(smem_addr), "l"(gptr), "r"(sz));
}

// ---------------- setup ----------------
__global__ void k_zero() {
    int i = blockIdx.x * blockDim.x + threadIdx.x;
    if (i < NN) { g_degin[i] = 0; g_degout[i] = 0; }
}

__global__ void k_hist(const int* __restrict__ src, const int* __restrict__ dst) {
    int e = blockIdx.x * blockDim.x + threadIdx.x;
    if (e < EE) {
        atomicAdd(&g_degout[src[e]], 1);
        atomicAdd(&g_degin[dst[e]], 1);
    }
}

__global__ void k_norms() {
    int i = blockIdx.x * blockDim.x + threadIdx.x;
    if (i < NN) {
        g_norm_src[i] = rsqrtf(fmaxf((float)g_degout[i], 1.0f));
        g_norm_dst[i] = rsqrtf(fmaxf((float)g_degin[i], 1.0f));
    }
    if (i < 2 * DD) g_stats[i] = 0.f;
    if (i < DD) g_zero[i] = 0.f;
}

// layer-0 X split: node_feats -> g_xh/g_xl
__global__ void k_xprep(const float* __restrict__ X) {
    int idx = blockIdx.x * blockDim.x + threadIdx.x;  // NN*32 float4s
    if (idx >= NN * 32) return;
    int row = idx >> 5, j4 = idx & 31;
    float4 v = ((const float4*)X)[idx];
    split_store(g_xh + (size_t)row * DD + j4 * 4, g_xl + (size_t)row * DD + j4 * 4, v);
}

// W split (optionally cs-scaled): W1,W2 -> g_w1h/l, g_w2h/l
__global__ void k_wsplit(const float* __restrict__ W1, const float* __restrict__ W2,
                         int use_cs) {
    int idx = blockIdx.x * blockDim.x + threadIdx.x;  // DD*32 float4s
    if (idx >= DD * 32) return;
    int k = idx >> 5, c4 = idx & 31;
    float s = use_cs ? g_cs[k] : 1.0f;
    float4 v1 = ((const float4*)W1)[idx];
    float4 v2 = ((const float4*)W2)[idx];
    v1.x *= s; v1.y *= s; v1.z *= s; v1.w *= s;
    v2.x *= s; v2.y *= s; v2.z *= s; v2.w *= s;
    split_store(g_w1h + k * DD + c4 * 4, g_w1l + k * DD + c4 * 4, v1);
    split_store(g_w2h + k * DD + c4 * 4, g_w2l + k * DD + c4 * 4, v2);
}

// ---------------- multi-block scan ----------------
__global__ void k_scan1() {
    __shared__ int sh[256];
    int tid = threadIdx.x;
    int i = blockIdx.x * 256 + tid;
    int v = (i < NN) ? g_degin[i] : 0;
    if (i < NN) g_cursor[i] = 0;
    sh[tid] = v;
    __syncthreads();
    for (int off = 128; off > 0; off >>= 1) {
        if (tid < off) sh[tid] += sh[tid + off];
        __syncthreads();
    }
    if (tid == 0) g_bsum[blockIdx.x] = sh[0];
}

__global__ void k_scan2() {
    __shared__ int sh[256];
    int tid = threadIdx.x;
    int v = (tid < SCAN_B) ? g_bsum[tid] : 0;
    sh[tid] = v;
    __syncthreads();
    for (int off = 1; off < 256; off <<= 1) {
        int t = (tid >= off) ? sh[tid - off] : 0;
        __syncthreads();
        sh[tid] += t;
        __syncthreads();
    }
    if (tid < SCAN_B) g_boff[tid] = sh[tid] - v;
}

__global__ void k_scan3() {
    __shared__ int sh[256];
    int tid = threadIdx.x;
    int i = blockIdx.x * 256 + tid;
    int v = (i < NN) ? g_degin[i] : 0;
    sh[tid] = v;
    __syncthreads();
    for (int off = 1; off < 256; off <<= 1) {
        int t = (tid >= off) ? sh[tid - off] : 0;
        __syncthreads();
        sh[tid] += t;
        __syncthreads();
    }
    if (i < NN) g_rowstart[i] = sh[tid] - v + g_boff[blockIdx.x];
    if (blockIdx.x == 0 && tid == 0) g_rowstart[NN] = EE;
}

__global__ void k_place(const int* __restrict__ src, const int* __restrict__ dst) {
    int e = blockIdx.x * blockDim.x + threadIdx.x;
    if (e < EE) {
        int d = dst[e];
        int slot = atomicAdd(&g_cursor[d], 1);
        g_csr_src[g_rowstart[d] + slot] = src[e];
    }
}

__global__ void k_wbias(const float* __restrict__ W1, const float* __restrict__ W2,
                        const float* __restrict__ br) {
    int tid = threadIdx.x;   // 256
    int c = tid & (DD - 1);
    const float* W = (tid < DD) ? W1 : W2;
    float s = 0.f;
#pragma unroll 16
    for (int k = 0; k < DD; k++) s += g_cb[k] * W[k * DD + c];
    if (tid < DD) g_bc1[c] = s;
    else          g_bc2[c] = s + br[c];
}

// ---------------- dual GEMM: pre-split bf16 tensor cores + cp.async X pipeline ----------------
// Y1 = rs .* (X @ W1 + b1c);  Y2 = relu(X @ W2 + b2c)
// 256 thr / 8 warps (4m x 2n); K chunked by 64, double-buffered cp.async X.
__global__ void __launch_bounds__(256)
k_dualgemm(const float* __restrict__ b1c,
           const float* __restrict__ b2c,
           const float* __restrict__ rs,
           float* __restrict__ Y1, float* __restrict__ Y2,
           int nrows) {
    extern __shared__ __nv_bfloat16 smb[];
    // layout: W1h W1l W2h W2l (4 x 128*LDP) then X buffers: [buf0: Xh Xl][buf1: Xh Xl]
    __nv_bfloat16* Wt = smb;                  // 4 * 9216 elems
    __nv_bfloat16* Xb = smb + 4 * 128 * LDP;  // 4 * 9216 elems
    float* stage = (float*)Xb;                // 128*LDP floats (fits in X region)

    const int tid = threadIdx.x;
    const int w = tid >> 5;
    const int wr = (w & 3) * 32;
    const int wc = (w >> 2) * 32;
    const int r0 = blockIdx.x * 128;
    const int c0 = blockIdx.y * 64;

    unsigned xb_base = (unsigned)__cvta_generic_to_shared(Xb);

    // cp.async X chunk kc into buffer b (h then l halves)
#define LDX(kc, b) do {                                                       \
        _Pragma("unroll")                                                     \
        for (int i = 0; i < 8; i++) {                                         \
            int f = tid + 256 * i;            /* 0..2047 */                   \
            int half = f >> 10;               /* 0=h, 1=l */                  \
            int g = f & 1023;                                                 \
            int rl = g >> 3, j = g & 7;                                       \
            int row = r0 + rl;                                                \
            const __nv_bfloat16* gp = (half ? g_xl : g_xh)                    \
                + (size_t)row * DD + (kc) * 64 + j * 8;                       \
            unsigned sa = xb_base +                                           \
                (unsigned)(((b) * 2 + half) * 128 * LDP + rl * LDP + j * 8) * 2; \
            cp_async16(sa, gp, row < nrows);                                  \
        }                                                                     \
        asm volatile("cp.async.commit_group;");                               \
    } while (0)

    LDX(0, 0);

    // W tiles: 4 x (128 rows x 8 uint4) regular loads (overlap with cp.async)
#pragma unroll
    for (int i = 0; i < 16; i++) {
        int f = tid + 256 * i;                // 0..4095
        int t = f >> 10;                      // tile 0..3
        int g = f & 1023;
        int k = g >> 3, j = g & 7;
        const __nv_bfloat16* gw = (t == 0) ? g_w1h : (t == 1) ? g_w1l
                                 : (t == 2) ? g_w2h : g_w2l;
        uint4 v = *(const uint4*)(gw + (size_t)k * DD + c0 + j * 8);
        *(uint4*)&Wt[t * 128 * LDP + k * LDP + j * 8] = v;
    }

    LDX(1, 1);

    __nv_bfloat16* W1h = Wt;
    __nv_bfloat16* W1l = Wt + 128 * LDP;
    __nv_bfloat16* W2h = Wt + 2 * 128 * LDP;
    __nv_bfloat16* W2l = Wt + 3 * 128 * LDP;

    wmma::fragment<wmma::accumulator, 16, 16, 16, float> acc1[2][2], acc2[2][2];
#pragma unroll
    for (int i = 0; i < 2; i++)
#pragma unroll
        for (int j = 0; j < 2; j++) {
            wmma::fill_fragment(acc1[i][j], 0.f);
            wmma::fill_fragment(acc2[i][j], 0.f);
        }

#pragma unroll 1
    for (int kc = 0; kc < 2; kc++) {
        if (kc == 0) asm volatile("cp.async.wait_group 1;");
        else         asm volatile("cp.async.wait_group 0;");
        __syncthreads();   // chunk kc + W tiles visible to all warps

        __nv_bfloat16* Xh = Xb + (kc * 2) * 128 * LDP;
        __nv_bfloat16* Xl = Xh + 128 * LDP;

#pragma unroll
        for (int ks = 0; ks < 64; ks += 16) {
            wmma::fragment<wmma::matrix_a, 16, 16, 16, __nv_bfloat16, wmma::row_major> ah[2], al[2];
#pragma unroll
            for (int i = 0; i < 2; i++) {
                wmma::load_matrix_sync(ah[i], Xh + (wr + 16 * i) * LDP + ks, LDP);
                wmma::load_matrix_sync(al[i], Xl + (wr + 16 * i) * LDP + ks, LDP);
            }
            int kg = kc * 64 + ks;
#pragma unroll
            for (int j = 0; j < 2; j++) {
                wmma::fragment<wmma::matrix_b, 16, 16, 16, __nv_bfloat16, wmma::row_major> bh, bl;
                wmma::load_matrix_sync(bh, W1h + kg * LDP + wc + 16 * j, LDP);
                wmma::load_matrix_sync(bl, W1l + kg * LDP + wc + 16 * j, LDP);
#pragma unroll
                for (int i = 0; i < 2; i++) {
                    wmma::mma_sync(acc1[i][j], ah[i], bh, acc1[i][j]);
                    wmma::mma_sync(acc1[i][j], ah[i], bl, acc1[i][j]);
                    wmma::mma_sync(acc1[i][j], al[i], bh, acc1[i][j]);
                }
                wmma::load_matrix_sync(bh, W2h + kg * LDP + wc + 16 * j, LDP);
                wmma::load_matrix_sync(bl, W2l + kg * LDP + wc + 16 * j, LDP);
#pragma unroll
                for (int i = 0; i < 2; i++) {
                    wmma::mma_sync(acc2[i][j], ah[i], bh, acc2[i][j]);
                    wmma::mma_sync(acc2[i][j], ah[i], bl, acc2[i][j]);
                    wmma::mma_sync(acc2[i][j], al[i], bh, acc2[i][j]);
                }
            }
        }
    }
#undef LDX

    // ---- epilogue via fp32 staging (reuses X smem) ----
    __syncthreads();
#pragma unroll
    for (int i = 0; i < 2; i++)
#pragma unroll
        for (int j = 0; j < 2; j++)
            wmma::store_matrix_sync(stage + (wr + 16 * i) * LDP + wc + 16 * j,
                                    acc1[i][j], LDP, wmma::mem_row_major);
    __syncthreads();
#pragma unroll
    for (int i = 0; i < 8; i++) {
        int f = tid + 256 * i;
        int rl = f >> 4, c4 = f & 15;
        int row = r0 + rl;
        if (row < nrows) {
            float s = rs[row];
            float4 vv = *(const float4*)&stage[rl * LDP + c4 * 4];
            float4 bb = ((const float4*)&b1c[c0])[c4];
            float4 o;
            o.x = (vv.x + bb.x) * s; o.y = (vv.y + bb.y) * s;
            o.z = (vv.z + bb.z) * s; o.w = (vv.w + bb.w) * s;
            ((float4*)&Y1[(size_t)row * DD + c0])[c4] = o;
        }
    }
    __syncthreads();
#pragma unroll
    for (int i = 0; i < 2; i++)
#pragma unroll
        for (int j = 0; j < 2; j++)
            wmma::store_matrix_sync(stage + (wr + 16 * i) * LDP + wc + 16 * j,
                                    acc2[i][j], LDP, wmma::mem_row_major);
    __syncthreads();
#pragma unroll
    for (int i = 0; i < 8; i++) {
        int f = tid + 256 * i;
        int rl = f >> 4, c4 = f & 15;
        int row = r0 + rl;
        if (row < nrows) {
            float4 vv = *(const float4*)&stage[rl * LDP + c4 * 4];
            float4 bb = ((const float4*)&b2c[c0])[c4];
            float4 o;
            o.x = fmaxf(vv.x + bb.x, 0.f);
            o.y = fmaxf(vv.y + bb.y, 0.f);
            o.z = fmaxf(vv.z + bb.z, 0.f);
            o.w = fmaxf(vv.w + bb.w, 0.f);
            ((float4*)&Y2[(size_t)row * DD + c0])[c4] = o;
        }
    }
}

// ---------------- CSR aggregation + combine + BN stats; emits bf16-split X ----------------
__global__ void k_agg(const float* __restrict__ bg, int zpool, int do_pool,
                      const int* __restrict__ gid, const int* __restrict__ mid) {
    __shared__ float ssum[8][DD];
    __shared__ float ssq[8][DD];
    int tid = threadIdx.x;
    int w = tid >> 5;
    int lane = tid & 31;

    if (zpool) {
        int gstep = gridDim.x * blockDim.x;
        int gidx = blockIdx.x * blockDim.x + tid;
        for (int i = gidx; i < GG * DD; i += gstep) g_gsum[i] = 0.f;
        for (int i = gidx; i < (MM + 1) * DD; i += gstep) g_msum[i] = 0.f;
        for (int i = gidx; i < GG; i += gstep) g_gcnt[i] = 0.f;
        for (int i = gidx; i < MM + 1; i += gstep) g_mcnt[i] = 0.f;
    }

    int node = blockIdx.x * 8 + w;
    float4 y = make_float4(0.f, 0.f, 0.f, 0.f);
    if (node < NN) {
        int e0 = g_rowstart[node], e1 = g_rowstart[node + 1];
        float4 acc[4];
#pragma unroll
        for (int i = 0; i < 4; i++) acc[i] = make_float4(0.f, 0.f, 0.f, 0.f);

        for (int base = e0; base < e1; base += 16) {
            int n = e1 - base;
            float4 v[16];
#pragma unroll
            for (int i = 0; i < 16; i++) {
                v[i] = make_float4(0.f, 0.f, 0.f, 0.f);
                if (i < n) {
                    int s = g_csr_src[base + i];
                    v[i] = ((const float4*)(g_bufB + (size_t)s * DD))[lane];
                }
            }
#pragma unroll
            for (int i = 0; i < 16; i++) {
                acc[i & 3].x += v[i].x; acc[i & 3].y += v[i].y;
                acc[i & 3].z += v[i].z; acc[i & 3].w += v[i].w;
            }
        }
        acc[0].x += acc[1].x + acc[2].x + acc[3].x;
        acc[0].y += acc[1].y + acc[2].y + acc[3].y;
        acc[0].z += acc[1].z + acc[2].z + acc[3].z;
        acc[0].w += acc[1].w + acc[2].w + acc[3].w;

        float nd = g_norm_dst[node];
        float4 b4 = ((const float4*)bg)[lane];
        float4 r = ((const float4*)(g_bufR + (size_t)node * DD))[lane];
        y.x = fmaxf(fmaf(acc[0].x, nd, b4.x), 0.f) + r.x;
        y.y = fmaxf(fmaf(acc[0].y, nd, b4.y), 0.f) + r.y;
        y.z = fmaxf(fmaf(acc[0].z, nd, b4.z), 0.f) + r.z;
        y.w = fmaxf(fmaf(acc[0].w, nd, b4.w), 0.f) + r.w;

        if (do_pool) {
            int gi = gid[node], mi = mid[node];
            atomicAdd(((float4*)(g_gsum + (size_t)gi * DD)) + lane, y);
            atomicAdd(((float4*)(g_msum + (size_t)mi * DD)) + lane, y);
            if (lane == 0) {
                atomicAdd(&g_gcnt[gi], 1.0f);
                atomicAdd(&g_mcnt[mi], 1.0f);
            }
        } else {
            // emit bf16 hi/lo for the next layer's GEMM
            split_store(g_xh + (size_t)node * DD + lane * 4,
                        g_xl + (size_t)node * DD + lane * 4, y);
        }
    }
    ((float4*)&ssum[w][0])[lane] = y;
    float4 y2 = make_float4(y.x * y.x, y.y * y.y, y.z * y.z, y.w * y.w);
    ((float4*)&ssq[w][0])[lane] = y2;
    __syncthreads();
    if (tid < DD) {
        float s = 0.f;
#pragma unroll
        for (int i = 0; i < 8; i++) s += ssum[i][tid];
        atomicAdd(&g_stats[tid], s);
    } else {
        int j = tid - DD;
        float s = 0.f;
#pragma unroll
        for (int i = 0; i < 8; i++) s += ssq[i][j];
        atomicAdd(&g_stats[DD + j], s);
    }
}

// ---------------- BN prep ----------------
__global__ void k_bnprep(const float* __restrict__ gamma, const float* __restrict__ beta) {
    int j = threadIdx.x;
    float invN = 1.0f / (float)NN;
    float mu = g_stats[j] * invN;
    float var = fmaxf(g_stats[DD + j] * invN - mu * mu, 0.f);
    float s = gamma[j] * rsqrtf(var + BN_EPS);
    g_cs[j] = s;
    g_cb[j] = beta[j] - mu * s;
    g_stats[j] = 0.f;
    g_stats[DD + j] = 0.f;
}

// ---------------- finalize: mean pools + layer-2 BN affine ----------------
__global__ void k_finalize(float* __restrict__ out_gf) {
    int idx = blockIdx.x * blockDim.x + threadIdx.x;
    if (idx >= (GG + MM) * DD) return;
    int row = idx / DD, j = idx % DD;
    float cs = g_cs[j], cb = g_cb[j];
    float v;
    if (row < GG) {
        v = cs * g_gsum[row * DD + j] / fmaxf(g_gcnt[row], 1.0f) + cb;
        out_gf[row * DD + j] = v;
    } else {
        int mrow = row - GG + 1;
        v = cs * g_msum[mrow * DD + j] / fmaxf(g_mcnt[mrow], 1.0f) + cb;
    }
    g_headin[idx] = v;
}

// ---------------- fp32 tiled GEMM with f32x2 (head MLP) ----------------
__global__ void k_gemm(const float* __restrict__ X, const float* __restrict__ W,
                       const float* __restrict__ bias,
                       float* __restrict__ Y, int nrows, int K, int ncols, int do_relu) {
    extern __shared__ float sm[];
    float* Ws = sm;
    float* Xs = sm + 128 * 128;
    const int tid = threadIdx.x;
    const int tx = tid & 31;
    const int ty = tid >> 5;
    const int r0 = blockIdx.x * 64;
    const int c0 = blockIdx.y * 128;

    unsigned long long acc[8][2];
#pragma unroll
    for (int m = 0; m < 8; m++) acc[m][0] = acc[m][1] = 0ull;

    for (int kb = 0; kb < K; kb += 128) {
#pragma unroll
        for (int i = 0; i < 16; i++) {
            int f = tid + 256 * i;
            int r = f >> 5, c4 = f & 31;
            ((float4*)Ws)[f] = *(const float4*)&W[(size_t)(kb + r) * ncols + c0 + c4 * 4];
        }
#pragma unroll
        for (int i = 0; i < 8; i++) {
            int f = tid + 256 * i;
            int m = f >> 5, k4 = f & 31;
            int row = r0 + m;
            float4 v = make_float4(0.f, 0.f, 0.f, 0.f);
            if (row < nrows) v = *(const float4*)&X[(size_t)row * K + kb + k4 * 4];
            ((float4*)Xs)[f] = v;
        }
        __syncthreads();

#pragma unroll 2
        for (int k = 0; k < 128; k += 4) {
            float4 xv[8];
#pragma unroll
            for (int m = 0; m < 8; m++)
                xv[m] = *(const float4*)&Xs[(ty * 8 + m) * 128 + k];
#pragma unroll
            for (int kk = 0; kk < 4; kk++) {
                ulonglong2 w = *(const ulonglong2*)&Ws[(k + kk) * 128 + tx * 4];
#pragma unroll
                for (int m = 0; m < 8; m++) {
                    float x = (kk == 0) ? xv[m].x : (kk == 1) ? xv[m].y
                            : (kk == 2) ? xv[m].z : xv[m].w;
                    unsigned long long xp = pack_dup(x);
                    ffma2(acc[m][0], xp, w.x);
                    ffma2(acc[m][1], xp, w.y);
                }
            }
        }
        __syncthreads();
    }

    float4 b4 = make_float4(0.f, 0.f, 0.f, 0.f);
    if (bias) b4 = *(const float4*)&bias[c0 + tx * 4];
#pragma unroll
    for (int m = 0; m < 8; m++) {
        int row = r0 + ty * 8 + m;
        if (row < nrows) {
            float2 p0 = unpack2(acc[m][0]);
            float2 p1 = unpack2(acc[m][1]);
            float4 o;
            o.x = p0.x + b4.x; o.y = p0.y + b4.y;
            o.z = p1.x + b4.z; o.w = p1.y + b4.w;
            if (do_relu) {
                o.x = fmaxf(o.x, 0.f); o.y = fmaxf(o.y, 0.f);
                o.z = fmaxf(o.z, 0.f); o.w = fmaxf(o.w, 0.f);
            }
            *(float4*)&Y[(size_t)row * ncols + c0 + tx * 4] = o;
        }
    }
}

// ---------------- launch ----------------
extern "C" void kernel_launch(void* const* d_in, const int* in_sizes, int n_in,
                              void* d_out, int out_size) {
    const float* node_feats = (const float*)d_in[0];
    const int*   src        = (const int*)d_in[1];
    const int*   dst        = (const int*)d_in[2];
    const int*   gid        = (const int*)d_in[3];
    const int*   mid        = (const int*)d_in[4];
    const float* Wg         = (const float*)d_in[5];
    const float* bg         = (const float*)d_in[6];
    const float* Wr         = (const float*)d_in[7];
    const float* br         = (const float*)d_in[8];
    const float* gamma      = (const float*)d_in[9];
    const float* beta       = (const float*)d_in[10];
    const float* W_feat     = (const float*)d_in[11];
    const float* b_feat     = (const float*)d_in[12];
    const float* W1         = (const float*)d_in[13];
    const float* b1         = (const float*)d_in[14];
    const float* W2         = (const float*)d_in[15];
    const float* b2         = (const float*)d_in[16];
    float* out = (float*)d_out;

    void *pns, *phin, *ph1, *ph2, *pB, *pR, *pbc1, *pbc2, *pz;
    cudaGetSymbolAddress(&pB, g_bufB);
    cudaGetSymbolAddress(&pR, g_bufR);
    cudaGetSymbolAddress(&pns, g_norm_src);
    cudaGetSymbolAddress(&phin, g_headin);
    cudaGetSymbolAddress(&ph1, g_head1);
    cudaGetSymbolAddress(&ph2, g_head2);
    cudaGetSymbolAddress(&pbc1, g_bc1);
    cudaGetSymbolAddress(&pbc2, g_bc2);
    cudaGetSymbolAddress(&pz, g_zero);

    const int SMEM_G = (128 * 128 + 64 * 128) * 4;   // 96 KB (head gemm)
    const int SMEM_D = 8 * 128 * LDP * 2;            // 147456 B (dual gemm)
    cudaFuncSetAttribute(k_gemm, cudaFuncAttributeMaxDynamicSharedMemorySize, SMEM_G);
    cudaFuncSetAttribute(k_dualgemm, cudaFuncAttributeMaxDynamicSharedMemorySize, SMEM_D);

    const int gemm_rows = (NN + 127) / 128;   // 391
    const int agg_blocks = (NN + 7) / 8;      // 6250

    // ---- setup ----
    k_zero<<<(NN + 255) / 256, 256>>>();
    k_hist<<<(EE + 255) / 256, 256>>>(src, dst);
    k_norms<<<(NN + 255) / 256, 256>>>();
    k_xprep<<<(NN * 32 + 255) / 256, 256>>>(node_feats);
    k_wsplit<<<(DD * 32 + 255) / 256, 256>>>(Wg, Wr, 0);

    // ---- layer-0 dual GEMM: b1c=0, b2c=br ----
    k_dualgemm<<<dim3(gemm_rows, 2), 256, SMEM_D>>>(
        (const float*)pz, br, (const float*)pns, (float*)pB, (float*)pR, NN);

    // ---- CSR build ----
    k_scan1<<<SCAN_B, 256>>>();
    k_scan2<<<1, 256>>>();
    k_scan3<<<SCAN_B, 256>>>();
    k_place<<<(EE + 255) / 256, 256>>>(src, dst);

    for (int l = 0; l < LL; l++) {
        if (l > 0) {
            k_wsplit<<<(DD * 32 + 255) / 256, 256>>>(
                Wg + (size_t)l * DD * DD, Wr + (size_t)l * DD * DD, 1);
            k_wbias<<<1, 2 * DD>>>(Wg + (size_t)l * DD * DD, Wr + (size_t)l * DD * DD,
                                   br + (size_t)l * DD);
            k_dualgemm<<<dim3(gemm_rows, 2), 256, SMEM_D>>>(
                (const float*)pbc1, (const float*)pbc2, (const float*)pns,
                (float*)pB, (float*)pR, NN);
        }

        k_agg<<<agg_blocks, 256>>>(bg + (size_t)l * DD,
                                   (l == 0) ? 1 : 0,
                                   (l == LL - 1) ? 1 : 0,
                                   gid, mid);

        k_bnprep<<<1, DD>>>(gamma + (size_t)l * DD, beta + (size_t)l * DD);
    }

    // ---- finalize ----
    k_finalize<<<((GG + MM) * DD + 255) / 256, 256>>>(out);

    // ---- head MLP on [graph_feats ; h_sub] = 2560 rows ----
    const int HR = GG + MM;
    const int hblocks = (HR + 63) / 64;
    k_gemm<<<dim3(hblocks, FFN / 128), 256, SMEM_G>>>(
        (const float*)phin, W_feat, b_feat, (float*)ph1, HR, DD, FFN, 0);
    k_gemm<<<dim3(hblocks, FFN / 128), 256, SMEM_G>>>(
        (const float*)ph1, W1, b1, (float*)ph2, HR, FFN, FFN, 1);
    k_gemm<<<dim3(hblocks, 1), 256, SMEM_G>>>(
        (const float*)ph2, W2, b2, out + (size_t)GG * DD, HR, FFN, DD, 0);
}

// round 15
// speedup vs baseline: 1.0535x; 1.0492x over previous
#include <cuda_runtime.h>
#include <cuda_bf16.h>
#include <mma.h>
#include <cstddef>

using namespace nvcuda;

#define NN 50000
#define EE 600000
#define GG 512
#define MM 2048
#define DD 128
#define FFN 256
#define LL 3
#define BN_EPS 1e-5f
#define SCAN_B 196   // ceil(NN/256)
#define LDP 72       // padded bf16 row length (144B) -> conflict-free ldmatrix
#define XROWS 256    // dualgemm row-tile

// ---------------- scratch (device globals) ----------------
__device__ float g_bufB[NN * DD];   // hw branch
__device__ float g_bufR[NN * DD];   // residual branch
__device__ __nv_bfloat16 g_xh[NN * DD];   // X hi (gemm input)
__device__ __nv_bfloat16 g_xl[NN * DD];   // X lo
__device__ __nv_bfloat16 g_w1h[DD * DD], g_w1l[DD * DD];
__device__ __nv_bfloat16 g_w2h[DD * DD], g_w2l[DD * DD];
__device__ int   g_degin[NN];
__device__ int   g_degout[NN];
__device__ int   g_cursor[NN];
__device__ int   g_rowstart[NN + 1];
__device__ int   g_csr_src[EE];
__device__ int   g_bsum[SCAN_B];
__device__ int   g_boff[SCAN_B];
__device__ float g_norm_src[NN];
__device__ float g_norm_dst[NN];
__device__ float g_stats[2 * DD];
__device__ float g_cs[DD];
__device__ float g_cb[DD];
__device__ float g_zero[DD];
__device__ float g_bc1[DD];         // cb @ Wg[l]
__device__ float g_bc2[DD];         // cb @ Wr[l] + br[l]
__device__ float g_gsum[GG * DD];
__device__ float g_gcnt[GG];
__device__ float g_msum[(MM + 1) * DD];
__device__ float g_mcnt[MM + 1];
__device__ float g_headin[(GG + MM) * DD];
__device__ float g_head1[(GG + MM) * FFN];
__device__ float g_head2[(GG + MM) * FFN];

// ---------------- helpers ----------------
__device__ __forceinline__ unsigned long long pack_dup(float x) {
    unsigned long long p;
    unsigned int xb = __float_as_uint(x);
    asm("mov.b64 %0, {%1, %1};" : "=l"(p) : "r"(xb));
    return p;
}
__device__ __forceinline__ void ffma2(unsigned long long& acc, unsigned long long a,
                                      unsigned long long b) {
    asm("fma.rn.f32x2 %0, %1, %2, %0;" : "+l"(acc) : "l"(a), "l"(b));
}
__device__ __forceinline__ float2 unpack2(unsigned long long a) {
    float lo, hi;
    asm("mov.b64 {%0, %1}, %2;" : "=f"(lo), "=f"(hi) : "l"(a));
    return make_float2(lo, hi);
}
__device__ __forceinline__ void split_store(__nv_bfloat16* ph, __nv_bfloat16* pl, float4 v) {
    __nv_bfloat162 h01 = __floats2bfloat162_rn(v.x, v.y);
    __nv_bfloat162 h23 = __floats2bfloat162_rn(v.z, v.w);
    float2 f01 = __bfloat1622float2(h01);
    float2 f23 = __bfloat1622float2(h23);
    __nv_bfloat162 l01 = __floats2bfloat162_rn(v.x - f01.x, v.y - f01.y);
    __nv_bfloat162 l23 = __floats2bfloat162_rn(v.z - f23.x, v.w - f23.y);
    uint2 hv, lv;
    hv.x = *(unsigned*)&h01; hv.y = *(unsigned*)&h23;
    lv.x = *(unsigned*)&l01; lv.y = *(unsigned*)&l23;
    *(uint2*)ph = hv;
    *(uint2*)pl = lv;
}
__device__ __forceinline__ void cp_async16(unsigned smem_addr, const void* gptr, bool valid) {
    int sz = valid ? 16 : 0;
    asm volatile("cp.async.cg.shared.global [%0], [%1], 16, %2;\n"
                 :: "r"(smem_addr), "l"(gptr), "r"(sz));
}

// ---------------- setup (fused: zero degrees + layer-0 W split) ----------------
__global__ void k_zero(const float* __restrict__ W1, const float* __restrict__ W2) {
    int i = blockIdx.x * blockDim.x + threadIdx.x;
    if (i < NN) { g_degin[i] = 0; g_degout[i] = 0; }
    if (i < DD * 32) {
        int k = i >> 5, c4 = i & 31;
        float4 v1 = ((const float4*)W1)[i];
        float4 v2 = ((const float4*)W2)[i];
        split_store(g_w1h + k * DD + c4 * 4, g_w1l + k * DD + c4 * 4, v1);
        split_store(g_w2h + k * DD + c4 * 4, g_w2l + k * DD + c4 * 4, v2);
    }
}

__global__ void k_hist(const int* __restrict__ src, const int* __restrict__ dst) {
    int e = blockIdx.x * blockDim.x + threadIdx.x;
    if (e < EE) {
        atomicAdd(&g_degout[src[e]], 1);
        atomicAdd(&g_degin[dst[e]], 1);
    }
}

// fused: norms + BN-stat zero + layer-0 X split (grid NN*32 threads)
__global__ void k_norms(const float* __restrict__ X) {
    int idx = blockIdx.x * blockDim.x + threadIdx.x;
    if (idx < NN * 32) {
        int row = idx >> 5, j4 = idx & 31;
        float4 v = ((const float4*)X)[idx];
        split_store(g_xh + (size_t)row * DD + j4 * 4,
                    g_xl + (size_t)row * DD + j4 * 4, v);
    }
    if (idx < NN) {
        g_norm_src[idx] = rsqrtf(fmaxf((float)g_degout[idx], 1.0f));
        g_norm_dst[idx] = rsqrtf(fmaxf((float)g_degin[idx], 1.0f));
    }
    if (idx < 2 * DD) g_stats[idx] = 0.f;
    if (idx < DD) g_zero[idx] = 0.f;
}

// W split (cs-scaled) for layers 1,2
__global__ void k_wsplit(const float* __restrict__ W1, const float* __restrict__ W2) {
    int idx = blockIdx.x * blockDim.x + threadIdx.x;
    if (idx >= DD * 32) return;
    int k = idx >> 5, c4 = idx & 31;
    float s = g_cs[k];
    float4 v1 = ((const float4*)W1)[idx];
    float4 v2 = ((const float4*)W2)[idx];
    v1.x *= s; v1.y *= s; v1.z *= s; v1.w *= s;
    v2.x *= s; v2.y *= s; v2.z *= s; v2.w *= s;
    split_store(g_w1h + k * DD + c4 * 4, g_w1l + k * DD + c4 * 4, v1);
    split_store(g_w2h + k * DD + c4 * 4, g_w2l + k * DD + c4 * 4, v2);
}

// ---------------- multi-block scan ----------------
__global__ void k_scan1() {
    __shared__ int sh[256];
    int tid = threadIdx.x;
    int i = blockIdx.x * 256 + tid;
    int v = (i < NN) ? g_degin[i] : 0;
    if (i < NN) g_cursor[i] = 0;
    sh[tid] = v;
    __syncthreads();
    for (int off = 128; off > 0; off >>= 1) {
        if (tid < off) sh[tid] += sh[tid + off];
        __syncthreads();
    }
    if (tid == 0) g_bsum[blockIdx.x] = sh[0];
}

__global__ void k_scan2() {
    __shared__ int sh[256];
    int tid = threadIdx.x;
    int v = (tid < SCAN_B) ? g_bsum[tid] : 0;
    sh[tid] = v;
    __syncthreads();
    for (int off = 1; off < 256; off <<= 1) {
        int t = (tid >= off) ? sh[tid - off] : 0;
        __syncthreads();
        sh[tid] += t;
        __syncthreads();
    }
    if (tid < SCAN_B) g_boff[tid] = sh[tid] - v;
}

__global__ void k_scan3() {
    __shared__ int sh[256];
    int tid = threadIdx.x;
    int i = blockIdx.x * 256 + tid;
    int v = (i < NN) ? g_degin[i] : 0;
    sh[tid] = v;
    __syncthreads();
    for (int off = 1; off < 256; off <<= 1) {
        int t = (tid >= off) ? sh[tid - off] : 0;
        __syncthreads();
        sh[tid] += t;
        __syncthreads();
    }
    if (i < NN) g_rowstart[i] = sh[tid] - v + g_boff[blockIdx.x];
    if (blockIdx.x == 0 && tid == 0) g_rowstart[NN] = EE;
}

__global__ void k_place(const int* __restrict__ src, const int* __restrict__ dst) {
    int e = blockIdx.x * blockDim.x + threadIdx.x;
    if (e < EE) {
        int d = dst[e];
        int slot = atomicAdd(&g_cursor[d], 1);
        g_csr_src[g_rowstart[d] + slot] = src[e];
    }
}

__global__ void k_wbias(const float* __restrict__ W1, const float* __restrict__ W2,
                        const float* __restrict__ br) {
    int tid = threadIdx.x;   // 256
    int c = tid & (DD - 1);
    const float* W = (tid < DD) ? W1 : W2;
    float s = 0.f;
#pragma unroll 16
    for (int k = 0; k < DD; k++) s += g_cb[k] * W[k * DD + c];
    if (tid < DD) g_bc1[c] = s;
    else          g_bc2[c] = s + br[c];
}

// ---------------- dual GEMM: pre-split bf16 tensor cores, 256-row tile, M_w=4 ----------------
// Y1 = rs .* (X @ W1 + b1c);  Y2 = relu(X @ W2 + b2c)
// 8 warps (4m x 2n), each warp 64 rows x 32 cols x 2 matrices.
// Per k-step per warp: 16 frag loads for 48 MMAs (was 12:24).
__global__ void __launch_bounds__(256, 1)
k_dualgemm(const float* __restrict__ b1c,
           const float* __restrict__ b2c,
           const float* __restrict__ rs,
           float* __restrict__ Y1, float* __restrict__ Y2,
           int nrows) {
    extern __shared__ __nv_bfloat16 smb[];
    __nv_bfloat16* Wt = smb;                  // 4 * 128*LDP (72 KB)
    __nv_bfloat16* Xb = smb + 4 * 128 * LDP;  // 2 buf * 2 hl * XROWS*LDP (144 KB)
    float* stage = (float*)Xb;                // XROWS*LDP floats (73.7 KB, fits)

    const int tid = threadIdx.x;
    const int w = tid >> 5;
    const int wr = (w & 3) * 64;     // 4 m-warps, 64 rows each
    const int wc = (w >> 2) * 32;    // 2 n-warps, 32 cols each
    const int r0 = blockIdx.x * XROWS;
    const int c0 = blockIdx.y * 64;

    unsigned xb_base = (unsigned)__cvta_generic_to_shared(Xb);

    // cp.async X chunk kc (64 K-cols) into buffer b: 2 halves x 256 rows x 8 x 16B
#define LDX(kc, b) do {                                                        \
        _Pragma("unroll")                                                      \
        for (int i = 0; i < 16; i++) {                                         \
            int f = tid + 256 * i;            /* 0..4095 */                    \
            int half = f >> 11;               /* 0=h, 1=l */                   \
            int g = f & 2047;                                                  \
            int rl = g >> 3, j = g & 7;                                        \
            int row = r0 + rl;                                                 \
            const __nv_bfloat16* gp = (half ? g_xl : g_xh)                     \
                + (size_t)row * DD + (kc) * 64 + j * 8;                        \
            unsigned sa = xb_base +                                            \
                (unsigned)(((b) * 2 + half) * XROWS * LDP + rl * LDP + j * 8) * 2; \
            cp_async16(sa, gp, row < nrows);                                   \
        }                                                                      \
        asm volatile("cp.async.commit_group;");                                \
    } while (0)

    LDX(0, 0);

    // W tiles: 4 x (128 rows x 8 uint4) regular loads (overlap with cp.async)
#pragma unroll
    for (int i = 0; i < 16; i++) {
        int f = tid + 256 * i;                // 0..4095
        int t = f >> 10;                      // tile 0..3
        int g = f & 1023;
        int k = g >> 3, j = g & 7;
        const __nv_bfloat16* gw = (t == 0) ? g_w1h : (t == 1) ? g_w1l
                                 : (t == 2) ? g_w2h : g_w2l;
        uint4 v = *(const uint4*)(gw + (size_t)k * DD + c0 + j * 8);
        *(uint4*)&Wt[t * 128 * LDP + k * LDP + j * 8] = v;
    }

    LDX(1, 1);

    __nv_bfloat16* W1h = Wt;
    __nv_bfloat16* W1l = Wt + 128 * LDP;
    __nv_bfloat16* W2h = Wt + 2 * 128 * LDP;
    __nv_bfloat16* W2l = Wt + 3 * 128 * LDP;

    wmma::fragment<wmma::accumulator, 16, 16, 16, float> acc1[4][2], acc2[4][2];
#pragma unroll
    for (int i = 0; i < 4; i++)
#pragma unroll
        for (int j = 0; j < 2; j++) {
            wmma::fill_fragment(acc1[i][j], 0.f);
            wmma::fill_fragment(acc2[i][j], 0.f);
        }

#pragma unroll 1
    for (int kc = 0; kc < 2; kc++) {
        if (kc == 0) asm volatile("cp.async.wait_group 1;");
        else         asm volatile("cp.async.wait_group 0;");
        __syncthreads();   // chunk kc + W tiles visible

        __nv_bfloat16* Xh = Xb + (kc * 2) * XROWS * LDP;
        __nv_bfloat16* Xl = Xh + XROWS * LDP;

#pragma unroll
        for (int ks = 0; ks < 64; ks += 16) {
            wmma::fragment<wmma::matrix_a, 16, 16, 16, __nv_bfloat16, wmma::row_major> ah[4], al[4];
#pragma unroll
            for (int i = 0; i < 4; i++) {
                wmma::load_matrix_sync(ah[i], Xh + (wr + 16 * i) * LDP + ks, LDP);
                wmma::load_matrix_sync(al[i], Xl + (wr + 16 * i) * LDP + ks, LDP);
            }
            int kg = kc * 64 + ks;
#pragma unroll
            for (int j = 0; j < 2; j++) {
                wmma::fragment<wmma::matrix_b, 16, 16, 16, __nv_bfloat16, wmma::row_major> bh, bl;
                wmma::load_matrix_sync(bh, W1h + kg * LDP + wc + 16 * j, LDP);
                wmma::load_matrix_sync(bl, W1l + kg * LDP + wc + 16 * j, LDP);
#pragma unroll
                for (int i = 0; i < 4; i++) {
                    wmma::mma_sync(acc1[i][j], ah[i], bh, acc1[i][j]);
                    wmma::mma_sync(acc1[i][j], ah[i], bl, acc1[i][j]);
                    wmma::mma_sync(acc1[i][j], al[i], bh, acc1[i][j]);
                }
                wmma::load_matrix_sync(bh, W2h + kg * LDP + wc + 16 * j, LDP);
                wmma::load_matrix_sync(bl, W2l + kg * LDP + wc + 16 * j, LDP);
#pragma unroll
                for (int i = 0; i < 4; i++) {
                    wmma::mma_sync(acc2[i][j], ah[i], bh, acc2[i][j]);
                    wmma::mma_sync(acc2[i][j], ah[i], bl, acc2[i][j]);
                    wmma::mma_sync(acc2[i][j], al[i], bh, acc2[i][j]);
                }
            }
        }
    }
#undef LDX

    // ---- epilogue via fp32 staging (reuses X smem) ----
    __syncthreads();
#pragma unroll
    for (int i = 0; i < 4; i++)
#pragma unroll
        for (int j = 0; j < 2; j++)
            wmma::store_matrix_sync(stage + (wr + 16 * i) * LDP + wc + 16 * j,
                                    acc1[i][j], LDP, wmma::mem_row_major);
    __syncthreads();
#pragma unroll
    for (int i = 0; i < 16; i++) {
        int f = tid + 256 * i;                // XROWS*16 float4
        int rl = f >> 4, c4 = f & 15;
        int row = r0 + rl;
        if (row < nrows) {
            float s = rs[row];
            float4 vv = *(const float4*)&stage[rl * LDP + c4 * 4];
            float4 bb = ((const float4*)&b1c[c0])[c4];
            float4 o;
            o.x = (vv.x + bb.x) * s; o.y = (vv.y + bb.y) * s;
            o.z = (vv.z + bb.z) * s; o.w = (vv.w + bb.w) * s;
            ((float4*)&Y1[(size_t)row * DD + c0])[c4] = o;
        }
    }
    __syncthreads();
#pragma unroll
    for (int i = 0; i < 4; i++)
#pragma unroll
        for (int j = 0; j < 2; j++)
            wmma::store_matrix_sync(stage + (wr + 16 * i) * LDP + wc + 16 * j,
                                    acc2[i][j], LDP, wmma::mem_row_major);
    __syncthreads();
#pragma unroll
    for (int i = 0; i < 16; i++) {
        int f = tid + 256 * i;
        int rl = f >> 4, c4 = f & 15;
        int row = r0 + rl;
        if (row < nrows) {
            float4 vv = *(const float4*)&stage[rl * LDP + c4 * 4];
            float4 bb = ((const float4*)&b2c[c0])[c4];
            float4 o;
            o.x = fmaxf(vv.x + bb.x, 0.f);
            o.y = fmaxf(vv.y + bb.y, 0.f);
            o.z = fmaxf(vv.z + bb.z, 0.f);
            o.w = fmaxf(vv.w + bb.w, 0.f);
            ((float4*)&Y2[(size_t)row * DD + c0])[c4] = o;
        }
    }
}

// ---------------- CSR aggregation + combine + BN stats; emits bf16-split X ----------------
__global__ void k_agg(const float* __restrict__ bg, int zpool, int do_pool,
                      const int* __restrict__ gid, const int* __restrict__ mid) {
    __shared__ float ssum[8][DD];
    __shared__ float ssq[8][DD];
    int tid = threadIdx.x;
    int w = tid >> 5;
    int lane = tid & 31;

    if (zpool) {
        int gstep = gridDim.x * blockDim.x;
        int gidx = blockIdx.x * blockDim.x + tid;
        for (int i = gidx; i < GG * DD; i += gstep) g_gsum[i] = 0.f;
        for (int i = gidx; i < (MM + 1) * DD; i += gstep) g_msum[i] = 0.f;
        for (int i = gidx; i < GG; i += gstep) g_gcnt[i] = 0.f;
        for (int i = gidx; i < MM + 1; i += gstep) g_mcnt[i] = 0.f;
    }

    int node = blockIdx.x * 8 + w;
    float4 y = make_float4(0.f, 0.f, 0.f, 0.f);
    if (node < NN) {
        int e0 = g_rowstart[node], e1 = g_rowstart[node + 1];
        float4 acc[4];
#pragma unroll
        for (int i = 0; i < 4; i++) acc[i] = make_float4(0.f, 0.f, 0.f, 0.f);

        for (int base = e0; base < e1; base += 16) {
            int n = e1 - base;
            float4 v[16];
#pragma unroll
            for (int i = 0; i < 16; i++) {
                v[i] = make_float4(0.f, 0.f, 0.f, 0.f);
                if (i < n) {
                    int s = g_csr_src[base + i];
                    v[i] = ((const float4*)(g_bufB + (size_t)s * DD))[lane];
                }
            }
#pragma unroll
            for (int i = 0; i < 16; i++) {
                acc[i & 3].x += v[i].x; acc[i & 3].y += v[i].y;
                acc[i & 3].z += v[i].z; acc[i & 3].w += v[i].w;
            }
        }
        acc[0].x += acc[1].x + acc[2].x + acc[3].x;
        acc[0].y += acc[1].y + acc[2].y + acc[3].y;
        acc[0].z += acc[1].z + acc[2].z + acc[3].z;
        acc[0].w += acc[1].w + acc[2].w + acc[3].w;

        float nd = g_norm_dst[node];
        float4 b4 = ((const float4*)bg)[lane];
        float4 r = ((const float4*)(g_bufR + (size_t)node * DD))[lane];
        y.x = fmaxf(fmaf(acc[0].x, nd, b4.x), 0.f) + r.x;
        y.y = fmaxf(fmaf(acc[0].y, nd, b4.y), 0.f) + r.y;
        y.z = fmaxf(fmaf(acc[0].z, nd, b4.z), 0.f) + r.z;
        y.w = fmaxf(fmaf(acc[0].w, nd, b4.w), 0.f) + r.w;

        if (do_pool) {
            int gi = gid[node], mi = mid[node];
            atomicAdd(((float4*)(g_gsum + (size_t)gi * DD)) + lane, y);
            atomicAdd(((float4*)(g_msum + (size_t)mi * DD)) + lane, y);
            if (lane == 0) {
                atomicAdd(&g_gcnt[gi], 1.0f);
                atomicAdd(&g_mcnt[mi], 1.0f);
            }
        } else {
            split_store(g_xh + (size_t)node * DD + lane * 4,
                        g_xl + (size_t)node * DD + lane * 4, y);
        }
    }
    ((float4*)&ssum[w][0])[lane] = y;
    float4 y2 = make_float4(y.x * y.x, y.y * y.y, y.z * y.z, y.w * y.w);
    ((float4*)&ssq[w][0])[lane] = y2;
    __syncthreads();
    if (tid < DD) {
        float s = 0.f;
#pragma unroll
        for (int i = 0; i < 8; i++) s += ssum[i][tid];
        atomicAdd(&g_stats[tid], s);
    } else {
        int j = tid - DD;
        float s = 0.f;
#pragma unroll
        for (int i = 0; i < 8; i++) s += ssq[i][j];
        atomicAdd(&g_stats[DD + j], s);
    }
}

// ---------------- BN prep ----------------
__global__ void k_bnprep(const float* __restrict__ gamma, const float* __restrict__ beta) {
    int j = threadIdx.x;
    float invN = 1.0f / (float)NN;
    float mu = g_stats[j] * invN;
    float var = fmaxf(g_stats[DD + j] * invN - mu * mu, 0.f);
    float s = gamma[j] * rsqrtf(var + BN_EPS);
    g_cs[j] = s;
    g_cb[j] = beta[j] - mu * s;
    g_stats[j] = 0.f;
    g_stats[DD + j] = 0.f;
}

// ---------------- finalize: mean pools + layer-2 BN affine ----------------
__global__ void k_finalize(float* __restrict__ out_gf) {
    int idx = blockIdx.x * blockDim.x + threadIdx.x;
    if (idx >= (GG + MM) * DD) return;
    int row = idx / DD, j = idx % DD;
    float cs = g_cs[j], cb = g_cb[j];
    float v;
    if (row < GG) {
        v = cs * g_gsum[row * DD + j] / fmaxf(g_gcnt[row], 1.0f) + cb;
        out_gf[row * DD + j] = v;
    } else {
        int mrow = row - GG + 1;
        v = cs * g_msum[mrow * DD + j] / fmaxf(g_mcnt[mrow], 1.0f) + cb;
    }
    g_headin[idx] = v;
}

// ---------------- fp32 tiled GEMM with f32x2 (head MLP) ----------------
__global__ void k_gemm(const float* __restrict__ X, const float* __restrict__ W,
                       const float* __restrict__ bias,
                       float* __restrict__ Y, int nrows, int K, int ncols, int do_relu) {
    extern __shared__ float sm[];
    float* Ws = sm;
    float* Xs = sm + 128 * 128;
    const int tid = threadIdx.x;
    const int tx = tid & 31;
    const int ty = tid >> 5;
    const int r0 = blockIdx.x * 64;
    const int c0 = blockIdx.y * 128;

    unsigned long long acc[8][2];
#pragma unroll
    for (int m = 0; m < 8; m++) acc[m][0] = acc[m][1] = 0ull;

    for (int kb = 0; kb < K; kb += 128) {
#pragma unroll
        for (int i = 0; i < 16; i++) {
            int f = tid + 256 * i;
            int r = f >> 5, c4 = f & 31;
            ((float4*)Ws)[f] = *(const float4*)&W[(size_t)(kb + r) * ncols + c0 + c4 * 4];
        }
#pragma unroll
        for (int i = 0; i < 8; i++) {
            int f = tid + 256 * i;
            int m = f >> 5, k4 = f & 31;
            int row = r0 + m;
            float4 v = make_float4(0.f, 0.f, 0.f, 0.f);
            if (row < nrows) v = *(const float4*)&X[(size_t)row * K + kb + k4 * 4];
            ((float4*)Xs)[f] = v;
        }
        __syncthreads();

#pragma unroll 2
        for (int k = 0; k < 128; k += 4) {
            float4 xv[8];
#pragma unroll
            for (int m = 0; m < 8; m++)
                xv[m] = *(const float4*)&Xs[(ty * 8 + m) * 128 + k];
#pragma unroll
            for (int kk = 0; kk < 4; kk++) {
                ulonglong2 w = *(const ulonglong2*)&Ws[(k + kk) * 128 + tx * 4];
#pragma unroll
                for (int m = 0; m < 8; m++) {
                    float x = (kk == 0) ? xv[m].x : (kk == 1) ? xv[m].y
                            : (kk == 2) ? xv[m].z : xv[m].w;
                    unsigned long long xp = pack_dup(x);
                    ffma2(acc[m][0], xp, w.x);
                    ffma2(acc[m][1], xp, w.y);
                }
            }
        }
        __syncthreads();
    }

    float4 b4 = make_float4(0.f, 0.f, 0.f, 0.f);
    if (bias) b4 = *(const float4*)&bias[c0 + tx * 4];
#pragma unroll
    for (int m = 0; m < 8; m++) {
        int row = r0 + ty * 8 + m;
        if (row < nrows) {
            float2 p0 = unpack2(acc[m][0]);
            float2 p1 = unpack2(acc[m][1]);
            float4 o;
            o.x = p0.x + b4.x; o.y = p0.y + b4.y;
            o.z = p1.x + b4.z; o.w = p1.y + b4.w;
            if (do_relu) {
                o.x = fmaxf(o.x, 0.f); o.y = fmaxf(o.y, 0.f);
                o.z = fmaxf(o.z, 0.f); o.w = fmaxf(o.w, 0.f);
            }
            *(float4*)&Y[(size_t)row * ncols + c0 + tx * 4] = o;
        }
    }
}

// ---------------- launch ----------------
extern "C" void kernel_launch(void* const* d_in, const int* in_sizes, int n_in,
                              void* d_out, int out_size) {
    const float* node_feats = (const float*)d_in[0];
    const int*   src        = (const int*)d_in[1];
    const int*   dst        = (const int*)d_in[2];
    const int*   gid        = (const int*)d_in[3];
    const int*   mid        = (const int*)d_in[4];
    const float* Wg         = (const float*)d_in[5];
    const float* bg         = (const float*)d_in[6];
    const float* Wr         = (const float*)d_in[7];
    const float* br         = (const float*)d_in[8];
    const float* gamma      = (const float*)d_in[9];
    const float* beta       = (const float*)d_in[10];
    const float* W_feat     = (const float*)d_in[11];
    const float* b_feat     = (const float*)d_in[12];
    const float* W1         = (const float*)d_in[13];
    const float* b1         = (const float*)d_in[14];
    const float* W2         = (const float*)d_in[15];
    const float* b2         = (const float*)d_in[16];
    float* out = (float*)d_out;

    void *pns, *phin, *ph1, *ph2, *pB, *pR, *pbc1, *pbc2, *pz;
    cudaGetSymbolAddress(&pB, g_bufB);
    cudaGetSymbolAddress(&pR, g_bufR);
    cudaGetSymbolAddress(&pns, g_norm_src);
    cudaGetSymbolAddress(&phin, g_headin);
    cudaGetSymbolAddress(&ph1, g_head1);
    cudaGetSymbolAddress(&ph2, g_head2);
    cudaGetSymbolAddress(&pbc1, g_bc1);
    cudaGetSymbolAddress(&pbc2, g_bc2);
    cudaGetSymbolAddress(&pz, g_zero);

    const int SMEM_G = (128 * 128 + 64 * 128) * 4;              // 96 KB (head gemm)
    const int SMEM_D = (4 * 128 * LDP + 4 * XROWS * LDP) * 2;   // 221184 B (dual gemm)
    cudaFuncSetAttribute(k_gemm, cudaFuncAttributeMaxDynamicSharedMemorySize, SMEM_G);
    cudaFuncSetAttribute(k_dualgemm, cudaFuncAttributeMaxDynamicSharedMemorySize, SMEM_D);

    const int gemm_rows = (NN + XROWS - 1) / XROWS;   // 196
    const int agg_blocks = (NN + 7) / 8;              // 6250

    // ---- setup (3 launches; dualgemm is #4 -> ncu-captured) ----
    k_zero<<<(NN + 255) / 256, 256>>>(Wg, Wr);
    k_hist<<<(EE + 255) / 256, 256>>>(src, dst);
    k_norms<<<(NN * 32 + 255) / 256, 256>>>(node_feats);

    // ---- layer-0 dual GEMM: b1c=0, b2c=br ----
    k_dualgemm<<<dim3(gemm_rows, 2), 256, SMEM_D>>>(
        (const float*)pz, br, (const float*)pns, (float*)pB, (float*)pR, NN);

    // ---- CSR build ----
    k_scan1<<<SCAN_B, 256>>>();
    k_scan2<<<1, 256>>>();
    k_scan3<<<SCAN_B, 256>>>();
    k_place<<<(EE + 255) / 256, 256>>>(src, dst);

    for (int l = 0; l < LL; l++) {
        if (l > 0) {
            k_wsplit<<<(DD * 32 + 255) / 256, 256>>>(
                Wg + (size_t)l * DD * DD, Wr + (size_t)l * DD * DD);
            k_wbias<<<1, 2 * DD>>>(Wg + (size_t)l * DD * DD, Wr + (size_t)l * DD * DD,
                                   br + (size_t)l * DD);
            k_dualgemm<<<dim3(gemm_rows, 2), 256, SMEM_D>>>(
                (const float*)pbc1, (const float*)pbc2, (const float*)pns,
                (float*)pB, (float*)pR, NN);
        }

        k_agg<<<agg_blocks, 256>>>(bg + (size_t)l * DD,
                                   (l == 0) ? 1 : 0,
                                   (l == LL - 1) ? 1 : 0,
                                   gid, mid);

        k_bnprep<<<1, DD>>>(gamma + (size_t)l * DD, beta + (size_t)l * DD);
    }

    // ---- finalize ----
    k_finalize<<<((GG + MM) * DD + 255) / 256, 256>>>(out);

    // ---- head MLP on [graph_feats ; h_sub] = 2560 rows ----
    const int HR = GG + MM;
    const int hblocks = (HR + 63) / 64;
    k_gemm<<<dim3(hblocks, FFN / 128), 256, SMEM_G>>>(
        (const float*)phin, W_feat, b_feat, (float*)ph1, HR, DD, FFN, 0);
    k_gemm<<<dim3(hblocks, FFN / 128), 256, SMEM_G>>>(
        (const float*)ph1, W1, b1, (float*)ph2, HR, FFN, FFN, 1);
    k_gemm<<<dim3(hblocks, 1), 256, SMEM_G>>>(
        (const float*)ph2, W2, b2, out + (size_t)GG * DD, HR, FFN, DD, 0);
}

// round 16
// speedup vs baseline: 1.0542x; 1.0007x over previous
#include <cuda_runtime.h>
#include <cuda_bf16.h>
#include <mma.h>
#include <cstddef>

using namespace nvcuda;

#define NN 50000
#define EE 600000
#define GG 512
#define MM 2048
#define DD 128
#define FFN 256
#define LL 3
#define BN_EPS 1e-5f
#define SCAN_B 196   // ceil(NN/256)
#define LDP 72       // padded bf16 row length (144B) -> conflict-free ldmatrix
#define XROWS 256    // dualgemm row-tile

// ---------------- scratch (device globals) ----------------
__device__ float g_bufB[NN * DD];   // hw branch
__device__ float g_bufR[NN * DD];   // residual branch
__device__ __nv_bfloat16 g_xh[NN * DD];   // X hi (gemm input)
__device__ __nv_bfloat16 g_xl[NN * DD];   // X lo
__device__ __nv_bfloat16 g_w1h[DD * DD], g_w1l[DD * DD];
__device__ __nv_bfloat16 g_w2h[DD * DD], g_w2l[DD * DD];
__device__ int   g_degin[NN];
__device__ int   g_degout[NN];
__device__ int   g_cursor[NN];
__device__ int   g_rowstart[NN + 1];
__device__ int   g_csr_src[EE];
__device__ int   g_bsum[SCAN_B];
__device__ int   g_boff[SCAN_B];
__device__ float g_norm_src[NN];
__device__ float g_norm_dst[NN];
__device__ float g_stats[2 * DD];
__device__ float g_cs[DD];
__device__ float g_cb[DD];
__device__ float g_zero[DD];
__device__ float g_bc1[DD];         // cb @ Wg[l]
__device__ float g_bc2[DD];         // cb @ Wr[l] + br[l]
__device__ float g_gsum[GG * DD];
__device__ float g_gcnt[GG];
__device__ float g_msum[(MM + 1) * DD];
__device__ float g_mcnt[MM + 1];
__device__ float g_headin[(GG + MM) * DD];
__device__ float g_head1[(GG + MM) * FFN];
__device__ float g_head2[(GG + MM) * FFN];

// ---------------- helpers ----------------
__device__ __forceinline__ unsigned long long pack_dup(float x) {
    unsigned long long p;
    unsigned int xb = __float_as_uint(x);
    asm("mov.b64 %0, {%1, %1};" : "=l"(p) : "r"(xb));
    return p;
}
__device__ __forceinline__ void ffma2(unsigned long long& acc, unsigned long long a,
                                      unsigned long long b) {
    asm("fma.rn.f32x2 %0, %1, %2, %0;" : "+l"(acc) : "l"(a), "l"(b));
}
__device__ __forceinline__ float2 unpack2(unsigned long long a) {
    float lo, hi;
    asm("mov.b64 {%0, %1}, %2;" : "=f"(lo), "=f"(hi) : "l"(a));
    return make_float2(lo, hi);
}
__device__ __forceinline__ void split_store(__nv_bfloat16* ph, __nv_bfloat16* pl, float4 v) {
    __nv_bfloat162 h01 = __floats2bfloat162_rn(v.x, v.y);
    __nv_bfloat162 h23 = __floats2bfloat162_rn(v.z, v.w);
    float2 f01 = __bfloat1622float2(h01);
    float2 f23 = __bfloat1622float2(h23);
    __nv_bfloat162 l01 = __floats2bfloat162_rn(v.x - f01.x, v.y - f01.y);
    __nv_bfloat162 l23 = __floats2bfloat162_rn(v.z - f23.x, v.w - f23.y);
    uint2 hv, lv;
    hv.x = *(unsigned*)&h01; hv.y = *(unsigned*)&h23;
    lv.x = *(unsigned*)&l01; lv.y = *(unsigned*)&l23;
    *(uint2*)ph = hv;
    *(uint2*)pl = lv;
}
__device__ __forceinline__ void cp_async16(unsigned smem_addr, const void* gptr, bool valid) {
    int sz = valid ? 16 : 0;
    asm volatile("cp.async.cg.shared.global [%0], [%1], 16, %2;\n"
                 :: "r"(smem_addr), "l"(gptr), "r"(sz));
}

// ---------------- setup (fused: zero degrees + layer-0 W split) ----------------
__global__ void k_zero(const float* __restrict__ W1, const float* __restrict__ W2) {
    int i = blockIdx.x * blockDim.x + threadIdx.x;
    if (i < NN) { g_degin[i] = 0; g_degout[i] = 0; }
    if (i < DD * 32) {
        int k = i >> 5, c4 = i & 31;
        float4 v1 = ((const float4*)W1)[i];
        float4 v2 = ((const float4*)W2)[i];
        split_store(g_w1h + k * DD + c4 * 4, g_w1l + k * DD + c4 * 4, v1);
        split_store(g_w2h + k * DD + c4 * 4, g_w2l + k * DD + c4 * 4, v2);
    }
}

__global__ void k_hist(const int* __restrict__ src, const int* __restrict__ dst) {
    int e = blockIdx.x * blockDim.x + threadIdx.x;
    if (e < EE) {
        atomicAdd(&g_degout[src[e]], 1);
        atomicAdd(&g_degin[dst[e]], 1);
    }
}

// fused: norms + BN-stat zero + layer-0 X split
__global__ void k_norms(const float* __restrict__ X) {
    int idx = blockIdx.x * blockDim.x + threadIdx.x;
    if (idx < NN * 32) {
        int row = idx >> 5, j4 = idx & 31;
        float4 v = ((const float4*)X)[idx];
        split_store(g_xh + (size_t)row * DD + j4 * 4,
                    g_xl + (size_t)row * DD + j4 * 4, v);
    }
    if (idx < NN) {
        g_norm_src[idx] = rsqrtf(fmaxf((float)g_degout[idx], 1.0f));
        g_norm_dst[idx] = rsqrtf(fmaxf((float)g_degin[idx], 1.0f));
    }
    if (idx < 2 * DD) g_stats[idx] = 0.f;
    if (idx < DD) g_zero[idx] = 0.f;
}

// W split (cs-scaled) for layers 1,2
__global__ void k_wsplit(const float* __restrict__ W1, const float* __restrict__ W2) {
    int idx = blockIdx.x * blockDim.x + threadIdx.x;
    if (idx >= DD * 32) return;
    int k = idx >> 5, c4 = idx & 31;
    float s = g_cs[k];
    float4 v1 = ((const float4*)W1)[idx];
    float4 v2 = ((const float4*)W2)[idx];
    v1.x *= s; v1.y *= s; v1.z *= s; v1.w *= s;
    v2.x *= s; v2.y *= s; v2.z *= s; v2.w *= s;
    split_store(g_w1h + k * DD + c4 * 4, g_w1l + k * DD + c4 * 4, v1);
    split_store(g_w2h + k * DD + c4 * 4, g_w2l + k * DD + c4 * 4, v2);
}

// ---------------- multi-block scan ----------------
__global__ void k_scan1() {
    __shared__ int sh[256];
    int tid = threadIdx.x;
    int i = blockIdx.x * 256 + tid;
    int v = (i < NN) ? g_degin[i] : 0;
    if (i < NN) g_cursor[i] = 0;
    sh[tid] = v;
    __syncthreads();
    for (int off = 128; off > 0; off >>= 1) {
        if (tid < off) sh[tid] += sh[tid + off];
        __syncthreads();
    }
    if (tid == 0) g_bsum[blockIdx.x] = sh[0];
}

__global__ void k_scan2() {
    __shared__ int sh[256];
    int tid = threadIdx.x;
    int v = (tid < SCAN_B) ? g_bsum[tid] : 0;
    sh[tid] = v;
    __syncthreads();
    for (int off = 1; off < 256; off <<= 1) {
        int t = (tid >= off) ? sh[tid - off] : 0;
        __syncthreads();
        sh[tid] += t;
        __syncthreads();
    }
    if (tid < SCAN_B) g_boff[tid] = sh[tid] - v;
}

__global__ void k_scan3() {
    __shared__ int sh[256];
    int tid = threadIdx.x;
    int i = blockIdx.x * 256 + tid;
    int v = (i < NN) ? g_degin[i] : 0;
    sh[tid] = v;
    __syncthreads();
    for (int off = 1; off < 256; off <<= 1) {
        int t = (tid >= off) ? sh[tid - off] : 0;
        __syncthreads();
        sh[tid] += t;
        __syncthreads();
    }
    if (i < NN) g_rowstart[i] = sh[tid] - v + g_boff[blockIdx.x];
    if (blockIdx.x == 0 && tid == 0) g_rowstart[NN] = EE;
}

__global__ void k_place(const int* __restrict__ src, const int* __restrict__ dst) {
    int e = blockIdx.x * blockDim.x + threadIdx.x;
    if (e < EE) {
        int d = dst[e];
        int slot = atomicAdd(&g_cursor[d], 1);
        g_csr_src[g_rowstart[d] + slot] = src[e];
    }
}

__global__ void k_wbias(const float* __restrict__ W1, const float* __restrict__ W2,
                        const float* __restrict__ br) {
    int tid = threadIdx.x;   // 256
    int c = tid & (DD - 1);
    const float* W = (tid < DD) ? W1 : W2;
    float s = 0.f;
#pragma unroll 16
    for (int k = 0; k < DD; k++) s += g_cb[k] * W[k * DD + c];
    if (tid < DD) g_bc1[c] = s;
    else          g_bc2[c] = s + br[c];
}

// ---------------- dual GEMM: pre-split bf16 tensor cores, 256-row tile ----------------
// Y1 = rs .* (X @ W1 + b1c);  Y2 = relu(X @ W2 + b2c)
// 8 warps (4m x 2n), warp = 64 rows x 32 cols x 2 matrices.
// b-fragments hoisted per k-step; a-pairs streamed per m-index (low liveness, no spills).
__global__ void __launch_bounds__(256, 1)
k_dualgemm(const float* __restrict__ b1c,
           const float* __restrict__ b2c,
           const float* __restrict__ rs,
           float* __restrict__ Y1, float* __restrict__ Y2,
           int nrows) {
    extern __shared__ __nv_bfloat16 smb[];
    __nv_bfloat16* Wt = smb;                  // 4 * 128*LDP (72 KB)
    __nv_bfloat16* Xb = smb + 4 * 128 * LDP;  // 2 buf * 2 hl * XROWS*LDP (144 KB)
    float* stage = (float*)Xb;                // XROWS*LDP floats

    const int tid = threadIdx.x;
    const int w = tid >> 5;
    const int wr = (w & 3) * 64;     // 4 m-warps, 64 rows each
    const int wc = (w >> 2) * 32;    // 2 n-warps, 32 cols each
    const int r0 = blockIdx.x * XROWS;
    const int c0 = blockIdx.y * 64;

    unsigned xb_base = (unsigned)__cvta_generic_to_shared(Xb);

#define LDX(kc, b) do {                                                        \
        _Pragma("unroll")                                                      \
        for (int i = 0; i < 16; i++) {                                         \
            int f = tid + 256 * i;                                             \
            int half = f >> 11;                                                \
            int g = f & 2047;                                                  \
            int rl = g >> 3, j = g & 7;                                        \
            int row = r0 + rl;                                                 \
            const __nv_bfloat16* gp = (half ? g_xl : g_xh)                     \
                + (size_t)row * DD + (kc) * 64 + j * 8;                        \
            unsigned sa = xb_base +                                            \
                (unsigned)(((b) * 2 + half) * XROWS * LDP + rl * LDP + j * 8) * 2; \
            cp_async16(sa, gp, row < nrows);                                   \
        }                                                                      \
        asm volatile("cp.async.commit_group;");                                \
    } while (0)

    LDX(0, 0);

    // W tiles: regular loads (overlap with cp.async)
#pragma unroll
    for (int i = 0; i < 16; i++) {
        int f = tid + 256 * i;
        int t = f >> 10;
        int g = f & 1023;
        int k = g >> 3, j = g & 7;
        const __nv_bfloat16* gw = (t == 0) ? g_w1h : (t == 1) ? g_w1l
                                 : (t == 2) ? g_w2h : g_w2l;
        uint4 v = *(const uint4*)(gw + (size_t)k * DD + c0 + j * 8);
        *(uint4*)&Wt[t * 128 * LDP + k * LDP + j * 8] = v;
    }

    LDX(1, 1);

    __nv_bfloat16* W1h = Wt;
    __nv_bfloat16* W1l = Wt + 128 * LDP;
    __nv_bfloat16* W2h = Wt + 2 * 128 * LDP;
    __nv_bfloat16* W2l = Wt + 3 * 128 * LDP;

    wmma::fragment<wmma::accumulator, 16, 16, 16, float> acc1[4][2], acc2[4][2];
#pragma unroll
    for (int i = 0; i < 4; i++)
#pragma unroll
        for (int j = 0; j < 2; j++) {
            wmma::fill_fragment(acc1[i][j], 0.f);
            wmma::fill_fragment(acc2[i][j], 0.f);
        }

#pragma unroll 1
    for (int kc = 0; kc < 2; kc++) {
        if (kc == 0) asm volatile("cp.async.wait_group 1;");
        else         asm volatile("cp.async.wait_group 0;");
        __syncthreads();

        __nv_bfloat16* Xh = Xb + (kc * 2) * XROWS * LDP;
        __nv_bfloat16* Xl = Xh + XROWS * LDP;

#pragma unroll
        for (int ks = 0; ks < 64; ks += 16) {
            int kg = kc * 64 + ks;
            // hoist all 8 b-fragments (reused by 4 m-indices)
            wmma::fragment<wmma::matrix_b, 16, 16, 16, __nv_bfloat16, wmma::row_major>
                b1h[2], b1l[2], b2h[2], b2l[2];
#pragma unroll
            for (int j = 0; j < 2; j++) {
                wmma::load_matrix_sync(b1h[j], W1h + kg * LDP + wc + 16 * j, LDP);
                wmma::load_matrix_sync(b1l[j], W1l + kg * LDP + wc + 16 * j, LDP);
                wmma::load_matrix_sync(b2h[j], W2h + kg * LDP + wc + 16 * j, LDP);
                wmma::load_matrix_sync(b2l[j], W2l + kg * LDP + wc + 16 * j, LDP);
            }
            // stream a-pairs one m-index at a time (low liveness)
#pragma unroll
            for (int i = 0; i < 4; i++) {
                wmma::fragment<wmma::matrix_a, 16, 16, 16, __nv_bfloat16, wmma::row_major> ah, al;
                wmma::load_matrix_sync(ah, Xh + (wr + 16 * i) * LDP + ks, LDP);
                wmma::load_matrix_sync(al, Xl + (wr + 16 * i) * LDP + ks, LDP);
#pragma unroll
                for (int j = 0; j < 2; j++) {
                    wmma::mma_sync(acc1[i][j], ah, b1h[j], acc1[i][j]);
                    wmma::mma_sync(acc1[i][j], ah, b1l[j], acc1[i][j]);
                    wmma::mma_sync(acc1[i][j], al, b1h[j], acc1[i][j]);
                    wmma::mma_sync(acc2[i][j], ah, b2h[j], acc2[i][j]);
                    wmma::mma_sync(acc2[i][j], ah, b2l[j], acc2[i][j]);
                    wmma::mma_sync(acc2[i][j], al, b2h[j], acc2[i][j]);
                }
            }
        }
    }
#undef LDX

    // ---- epilogue via fp32 staging (reuses X smem) ----
    __syncthreads();
#pragma unroll
    for (int i = 0; i < 4; i++)
#pragma unroll
        for (int j = 0; j < 2; j++)
            wmma::store_matrix_sync(stage + (wr + 16 * i) * LDP + wc + 16 * j,
                                    acc1[i][j], LDP, wmma::mem_row_major);
    __syncthreads();
#pragma unroll
    for (int i = 0; i < 16; i++) {
        int f = tid + 256 * i;
        int rl = f >> 4, c4 = f & 15;
        int row = r0 + rl;
        if (row < nrows) {
            float s = rs[row];
            float4 vv = *(const float4*)&stage[rl * LDP + c4 * 4];
            float4 bb = ((const float4*)&b1c[c0])[c4];
            float4 o;
            o.x = (vv.x + bb.x) * s; o.y = (vv.y + bb.y) * s;
            o.z = (vv.z + bb.z) * s; o.w = (vv.w + bb.w) * s;
            ((float4*)&Y1[(size_t)row * DD + c0])[c4] = o;
        }
    }
    __syncthreads();
#pragma unroll
    for (int i = 0; i < 4; i++)
#pragma unroll
        for (int j = 0; j < 2; j++)
            wmma::store_matrix_sync(stage + (wr + 16 * i) * LDP + wc + 16 * j,
                                    acc2[i][j], LDP, wmma::mem_row_major);
    __syncthreads();
#pragma unroll
    for (int i = 0; i < 16; i++) {
        int f = tid + 256 * i;
        int rl = f >> 4, c4 = f & 15;
        int row = r0 + rl;
        if (row < nrows) {
            float4 vv = *(const float4*)&stage[rl * LDP + c4 * 4];
            float4 bb = ((const float4*)&b2c[c0])[c4];
            float4 o;
            o.x = fmaxf(vv.x + bb.x, 0.f);
            o.y = fmaxf(vv.y + bb.y, 0.f);
            o.z = fmaxf(vv.z + bb.z, 0.f);
            o.w = fmaxf(vv.w + bb.w, 0.f);
            ((float4*)&Y2[(size_t)row * DD + c0])[c4] = o;
        }
    }
}

// ---------------- CSR aggregation + combine + BN stats; emits bf16-split X ----------------
__global__ void k_agg(const float* __restrict__ bg, int zpool, int do_pool,
                      const int* __restrict__ gid, const int* __restrict__ mid) {
    __shared__ float ssum[8][DD];
    __shared__ float ssq[8][DD];
    int tid = threadIdx.x;
    int w = tid >> 5;
    int lane = tid & 31;

    if (zpool) {
        int gstep = gridDim.x * blockDim.x;
        int gidx = blockIdx.x * blockDim.x + tid;
        for (int i = gidx; i < GG * DD; i += gstep) g_gsum[i] = 0.f;
        for (int i = gidx; i < (MM + 1) * DD; i += gstep) g_msum[i] = 0.f;
        for (int i = gidx; i < GG; i += gstep) g_gcnt[i] = 0.f;
        for (int i = gidx; i < MM + 1; i += gstep) g_mcnt[i] = 0.f;
    }

    int node = blockIdx.x * 8 + w;
    float4 y = make_float4(0.f, 0.f, 0.f, 0.f);
    if (node < NN) {
        int e0 = g_rowstart[node], e1 = g_rowstart[node + 1];
        float4 acc[4];
#pragma unroll
        for (int i = 0; i < 4; i++) acc[i] = make_float4(0.f, 0.f, 0.f, 0.f);

        for (int base = e0; base < e1; base += 16) {
            int n = e1 - base;
            float4 v[16];
#pragma unroll
            for (int i = 0; i < 16; i++) {
                v[i] = make_float4(0.f, 0.f, 0.f, 0.f);
                if (i < n) {
                    int s = g_csr_src[base + i];
                    v[i] = ((const float4*)(g_bufB + (size_t)s * DD))[lane];
                }
            }
#pragma unroll
            for (int i = 0; i < 16; i++) {
                acc[i & 3].x += v[i].x; acc[i & 3].y += v[i].y;
                acc[i & 3].z += v[i].z; acc[i & 3].w += v[i].w;
            }
        }
        acc[0].x += acc[1].x + acc[2].x + acc[3].x;
        acc[0].y += acc[1].y + acc[2].y + acc[3].y;
        acc[0].z += acc[1].z + acc[2].z + acc[3].z;
        acc[0].w += acc[1].w + acc[2].w + acc[3].w;

        float nd = g_norm_dst[node];
        float4 b4 = ((const float4*)bg)[lane];
        float4 r = ((const float4*)(g_bufR + (size_t)node * DD))[lane];
        y.x = fmaxf(fmaf(acc[0].x, nd, b4.x), 0.f) + r.x;
        y.y = fmaxf(fmaf(acc[0].y, nd, b4.y), 0.f) + r.y;
        y.z = fmaxf(fmaf(acc[0].z, nd, b4.z), 0.f) + r.z;
        y.w = fmaxf(fmaf(acc[0].w, nd, b4.w), 0.f) + r.w;

        if (do_pool) {
            int gi = gid[node], mi = mid[node];
            atomicAdd(((float4*)(g_gsum + (size_t)gi * DD)) + lane, y);
            atomicAdd(((float4*)(g_msum + (size_t)mi * DD)) + lane, y);
            if (lane == 0) {
                atomicAdd(&g_gcnt[gi], 1.0f);
                atomicAdd(&g_mcnt[mi], 1.0f);
            }
        } else {
            split_store(g_xh + (size_t)node * DD + lane * 4,
                        g_xl + (size_t)node * DD + lane * 4, y);
        }
    }
    ((float4*)&ssum[w][0])[lane] = y;
    float4 y2 = make_float4(y.x * y.x, y.y * y.y, y.z * y.z, y.w * y.w);
    ((float4*)&ssq[w][0])[lane] = y2;
    __syncthreads();
    if (tid < DD) {
        float s = 0.f;
#pragma unroll
        for (int i = 0; i < 8; i++) s += ssum[i][tid];
        atomicAdd(&g_stats[tid], s);
    } else {
        int j = tid - DD;
        float s = 0.f;
#pragma unroll
        for (int i = 0; i < 8; i++) s += ssq[i][j];
        atomicAdd(&g_stats[DD + j], s);
    }
}

// ---------------- BN prep ----------------
__global__ void k_bnprep(const float* __restrict__ gamma, const float* __restrict__ beta) {
    int j = threadIdx.x;
    float invN = 1.0f / (float)NN;
    float mu = g_stats[j] * invN;
    float var = fmaxf(g_stats[DD + j] * invN - mu * mu, 0.f);
    float s = gamma[j] * rsqrtf(var + BN_EPS);
    g_cs[j] = s;
    g_cb[j] = beta[j] - mu * s;
    g_stats[j] = 0.f;
    g_stats[DD + j] = 0.f;
}

// ---------------- finalize: mean pools + layer-2 BN affine ----------------
__global__ void k_finalize(float* __restrict__ out_gf) {
    int idx = blockIdx.x * blockDim.x + threadIdx.x;
    if (idx >= (GG + MM) * DD) return;
    int row = idx / DD, j = idx % DD;
    float cs = g_cs[j], cb = g_cb[j];
    float v;
    if (row < GG) {
        v = cs * g_gsum[row * DD + j] / fmaxf(g_gcnt[row], 1.0f) + cb;
        out_gf[row * DD + j] = v;
    } else {
        int mrow = row - GG + 1;
        v = cs * g_msum[mrow * DD + j] / fmaxf(g_mcnt[mrow], 1.0f) + cb;
    }
    g_headin[idx] = v;
}

// ---------------- fp32 tiled GEMM with f32x2 (head MLP) ----------------
__global__ void k_gemm(const float* __restrict__ X, const float* __restrict__ W,
                       const float* __restrict__ bias,
                       float* __restrict__ Y, int nrows, int K, int ncols, int do_relu) {
    extern __shared__ float sm[];
    float* Ws = sm;
    float* Xs = sm + 128 * 128;
    const int tid = threadIdx.x;
    const int tx = tid & 31;
    const int ty = tid >> 5;
    const int r0 = blockIdx.x * 64;
    const int c0 = blockIdx.y * 128;

    unsigned long long acc[8][2];
#pragma unroll
    for (int m = 0; m < 8; m++) acc[m][0] = acc[m][1] = 0ull;

    for (int kb = 0; kb < K; kb += 128) {
#pragma unroll
        for (int i = 0; i < 16; i++) {
            int f = tid + 256 * i;
            int r = f >> 5, c4 = f & 31;
            ((float4*)Ws)[f] = *(const float4*)&W[(size_t)(kb + r) * ncols + c0 + c4 * 4];
        }
#pragma unroll
        for (int i = 0; i < 8; i++) {
            int f = tid + 256 * i;
            int m = f >> 5, k4 = f & 31;
            int row = r0 + m;
            float4 v = make_float4(0.f, 0.f, 0.f, 0.f);
            if (row < nrows) v = *(const float4*)&X[(size_t)row * K + kb + k4 * 4];
            ((float4*)Xs)[f] = v;
        }
        __syncthreads();

#pragma unroll 2
        for (int k = 0; k < 128; k += 4) {
            float4 xv[8];
#pragma unroll
            for (int m = 0; m < 8; m++)
                xv[m] = *(const float4*)&Xs[(ty * 8 + m) * 128 + k];
#pragma unroll
            for (int kk = 0; kk < 4; kk++) {
                ulonglong2 w = *(const ulonglong2*)&Ws[(k + kk) * 128 + tx * 4];
#pragma unroll
                for (int m = 0; m < 8; m++) {
                    float x = (kk == 0) ? xv[m].x : (kk == 1) ? xv[m].y
                            : (kk == 2) ? xv[m].z : xv[m].w;
                    unsigned long long xp = pack_dup(x);
                    ffma2(acc[m][0], xp, w.x);
                    ffma2(acc[m][1], xp, w.y);
                }
            }
        }
        __syncthreads();
    }

    float4 b4 = make_float4(0.f, 0.f, 0.f, 0.f);
    if (bias) b4 = *(const float4*)&bias[c0 + tx * 4];
#pragma unroll
    for (int m = 0; m < 8; m++) {
        int row = r0 + ty * 8 + m;
        if (row < nrows) {
            float2 p0 = unpack2(acc[m][0]);
            float2 p1 = unpack2(acc[m][1]);
            float4 o;
            o.x = p0.x + b4.x; o.y = p0.y + b4.y;
            o.z = p1.x + b4.z; o.w = p1.y + b4.w;
            if (do_relu) {
                o.x = fmaxf(o.x, 0.f); o.y = fmaxf(o.y, 0.f);
                o.z = fmaxf(o.z, 0.f); o.w = fmaxf(o.w, 0.f);
            }
            *(float4*)&Y[(size_t)row * ncols + c0 + tx * 4] = o;
        }
    }
}

// ---------------- launch ----------------
extern "C" void kernel_launch(void* const* d_in, const int* in_sizes, int n_in,
                              void* d_out, int out_size) {
    const float* node_feats = (const float*)d_in[0];
    const int*   src        = (const int*)d_in[1];
    const int*   dst        = (const int*)d_in[2];
    const int*   gid        = (const int*)d_in[3];
    const int*   mid        = (const int*)d_in[4];
    const float* Wg         = (const float*)d_in[5];
    const float* bg         = (const float*)d_in[6];
    const float* Wr         = (const float*)d_in[7];
    const float* br         = (const float*)d_in[8];
    const float* gamma      = (const float*)d_in[9];
    const float* beta       = (const float*)d_in[10];
    const float* W_feat     = (const float*)d_in[11];
    const float* b_feat     = (const float*)d_in[12];
    const float* W1         = (const float*)d_in[13];
    const float* b1         = (const float*)d_in[14];
    const float* W2         = (const float*)d_in[15];
    const float* b2         = (const float*)d_in[16];
    float* out = (float*)d_out;

    void *pns, *phin, *ph1, *ph2, *pB, *pR, *pbc1, *pbc2, *pz;
    cudaGetSymbolAddress(&pB, g_bufB);
    cudaGetSymbolAddress(&pR, g_bufR);
    cudaGetSymbolAddress(&pns, g_norm_src);
    cudaGetSymbolAddress(&phin, g_headin);
    cudaGetSymbolAddress(&ph1, g_head1);
    cudaGetSymbolAddress(&ph2, g_head2);
    cudaGetSymbolAddress(&pbc1, g_bc1);
    cudaGetSymbolAddress(&pbc2, g_bc2);
    cudaGetSymbolAddress(&pz, g_zero);

    const int SMEM_G = (128 * 128 + 64 * 128) * 4;              // 96 KB (head gemm)
    const int SMEM_D = (4 * 128 * LDP + 4 * XROWS * LDP) * 2;   // 221184 B (dual gemm)
    cudaFuncSetAttribute(k_gemm, cudaFuncAttributeMaxDynamicSharedMemorySize, SMEM_G);
    cudaFuncSetAttribute(k_dualgemm, cudaFuncAttributeMaxDynamicSharedMemorySize, SMEM_D);

    const int gemm_rows = (NN + XROWS - 1) / XROWS;   // 196
    const int agg_blocks = (NN + 7) / 8;              // 6250

    // ---- setup (3 launches; dualgemm is #4 -> ncu-captured) ----
    k_zero<<<(NN + 255) / 256, 256>>>(Wg, Wr);
    k_hist<<<(EE + 255) / 256, 256>>>(src, dst);
    k_norms<<<(NN * 32 + 255) / 256, 256>>>(node_feats);

    // ---- layer-0 dual GEMM: b1c=0, b2c=br ----
    k_dualgemm<<<dim3(gemm_rows, 2), 256, SMEM_D>>>(
        (const float*)pz, br, (const float*)pns, (float*)pB, (float*)pR, NN);

    // ---- CSR build ----
    k_scan1<<<SCAN_B, 256>>>();
    k_scan2<<<1, 256>>>();
    k_scan3<<<SCAN_B, 256>>>();
    k_place<<<(EE + 255) / 256, 256>>>(src, dst);

    for (int l = 0; l < LL; l++) {
        if (l > 0) {
            k_wsplit<<<(DD * 32 + 255) / 256, 256>>>(
                Wg + (size_t)l * DD * DD, Wr + (size_t)l * DD * DD);
            k_wbias<<<1, 2 * DD>>>(Wg + (size_t)l * DD * DD, Wr + (size_t)l * DD * DD,
                                   br + (size_t)l * DD);
            k_dualgemm<<<dim3(gemm_rows, 2), 256, SMEM_D>>>(
                (const float*)pbc1, (const float*)pbc2, (const float*)pns,
                (float*)pB, (float*)pR, NN);
        }

        k_agg<<<agg_blocks, 256>>>(bg + (size_t)l * DD,
                                   (l == 0) ? 1 : 0,
                                   (l == LL - 1) ? 1 : 0,
                                   gid, mid);

        k_bnprep<<<1, DD>>>(gamma + (size_t)l * DD, beta + (size_t)l * DD);
    }

    // ---- finalize ----
    k_finalize<<<((GG + MM) * DD + 255) / 256, 256>>>(out);

    // ---- head MLP on [graph_feats ; h_sub] = 2560 rows ----
    const int HR = GG + MM;
    const int hblocks = (HR + 63) / 64;
    k_gemm<<<dim3(hblocks, FFN / 128), 256, SMEM_G>>>(
        (const float*)phin, W_feat, b_feat, (float*)ph1, HR, DD, FFN, 0);
    k_gemm<<<dim3(hblocks, FFN / 128), 256, SMEM_G>>>(
        (const float*)ph1, W1, b1, (float*)ph2, HR, FFN, FFN, 1);
    k_gemm<<<dim3(hblocks, 1), 256, SMEM_G>>>(
        (const float*)ph2, W2, b2, out + (size_t)GG * DD, HR, FFN, DD, 0);
}